// round 5
// baseline (speedup 1.0000x reference)
#include <cuda_runtime.h>
#include <mma.h>
#include <math.h>
#include <stdint.h>

using namespace nvcuda;

#define TOK   2048
#define DIMK  1024
#define HIDN  4096
#define NEXP  7
#define NE_ALL 8
#define ALPHA_C 2.0f

#define BM 128
#define NTHREADS 256

// ---------------------------------------------------------------------------
// Scratch
// ---------------------------------------------------------------------------
__device__ int   g_eidx[TOK];
__device__ float g_scale[TOK];
__device__ int   g_perm[TOK];
__device__ int   g_off[NEXP + 1];
__device__ __align__(128) float g_xr[(size_t)TOK * DIMK];
__device__ __align__(128) float g_hr[(size_t)TOK * HIDN];   // routed hidden (perm rows)
__device__ __align__(128) float g_hs[(size_t)TOK * HIDN];   // shared hidden (token rows)
// RNA-rounded weight copies (same layout as inputs; rounding only)
__device__ __align__(128) float g_wgt[(size_t)NEXP * DIMK * HIDN];
__device__ __align__(128) float g_wut[(size_t)NEXP * DIMK * HIDN];
__device__ __align__(128) float g_wdt[(size_t)NEXP * HIDN * DIMK];
__device__ __align__(128) float g_wsgt[(size_t)DIMK * HIDN];
__device__ __align__(128) float g_wsut[(size_t)DIMK * HIDN];
__device__ __align__(128) float g_wsdt[(size_t)HIDN * DIMK];

// ---------------------------------------------------------------------------
// helpers
// ---------------------------------------------------------------------------
__device__ __forceinline__ float rna_tf32(float x) {
    float r; asm("cvt.rna.tf32.f32 %0, %1;" : "=f"(r) : "f"(x)); return r;
}
__device__ __forceinline__ void cp_async16(void* smem_dst, const void* gmem_src) {
    uint32_t s = (uint32_t)__cvta_generic_to_shared(smem_dst);
    asm volatile("cp.async.cg.shared.global [%0], [%1], 16;\n" :: "r"(s), "l"(gmem_src));
}
__device__ __forceinline__ void cp_commit() { asm volatile("cp.async.commit_group;\n"); }
template <int N> __device__ __forceinline__ void cp_wait() {
    asm volatile("cp.async.wait_group %0;\n" :: "n"(N));
}
__device__ __forceinline__ float silu_f(float v) { return v / (1.0f + expf(-v)); }

// elementwise RNA rounding copy (float4 vectorized)
__global__ void round4_kernel(const float4* __restrict__ s, float4* __restrict__ d,
                              int n4) {
    int i = blockIdx.x * blockDim.x + threadIdx.x;
    if (i >= n4) return;
    float4 v = s[i];
    v.x = rna_tf32(v.x); v.y = rna_tf32(v.y);
    v.z = rna_tf32(v.z); v.w = rna_tf32(v.w);
    d[i] = v;
}

// ---------------------------------------------------------------------------
// Router (fp32 exact) + plan
// ---------------------------------------------------------------------------
__global__ void router_kernel(const float* __restrict__ x,
                              const float* __restrict__ wr) {
    int gw   = (blockIdx.x * blockDim.x + threadIdx.x) >> 5;
    int lane = threadIdx.x & 31;
    if (gw >= TOK) return;
    const float* xr = x + (size_t)gw * DIMK;
    float acc[NE_ALL];
#pragma unroll
    for (int e = 0; e < NE_ALL; e++) acc[e] = 0.f;
    for (int d = lane; d < DIMK; d += 32) {
        float xv = xr[d];
        const float4* w4 = reinterpret_cast<const float4*>(wr + (size_t)d * NE_ALL);
        float4 w0 = w4[0], w1 = w4[1];
        acc[0] += xv * w0.x; acc[1] += xv * w0.y;
        acc[2] += xv * w0.z; acc[3] += xv * w0.w;
        acc[4] += xv * w1.x; acc[5] += xv * w1.y;
        acc[6] += xv * w1.z; acc[7] += xv * w1.w;
    }
#pragma unroll
    for (int e = 0; e < NE_ALL; e++)
#pragma unroll
        for (int o = 16; o > 0; o >>= 1)
            acc[e] += __shfl_xor_sync(0xffffffffu, acc[e], o);
    if (lane == 0) {
        float m = acc[0]; int idx = 0;
#pragma unroll
        for (int e = 1; e < NE_ALL; e++)
            if (acc[e] > m) { m = acc[e]; idx = e; }
        float s = 0.f;
#pragma unroll
        for (int e = 0; e < NE_ALL; e++) s += expf(acc[e] - m);
        g_scale[gw] = ALPHA_C / s;
        g_eidx[gw]  = idx;
    }
}

__global__ void plan_kernel() {
    __shared__ int cnt[NEXP], offs[NEXP + 1], cur[NEXP];
    int tid = threadIdx.x;
    if (tid < NEXP) cnt[tid] = 0;
    __syncthreads();
    for (int t = tid; t < TOK; t += blockDim.x) {
        int e = g_eidx[t];
        if (e < NEXP) atomicAdd(&cnt[e], 1);
    }
    __syncthreads();
    if (tid == 0) {
        int o = 0;
        for (int e = 0; e < NEXP; e++) { offs[e] = o; cur[e] = o; o += cnt[e]; }
        offs[NEXP] = o;
    }
    __syncthreads();
    for (int t = tid; t < TOK; t += blockDim.x) {
        int e = g_eidx[t];
        if (e < NEXP) g_perm[atomicAdd(&cur[e], 1)] = t;
    }
    if (tid <= NEXP) g_off[tid] = offs[tid];
}

// ---------------------------------------------------------------------------
// Fused hidden kernel: H = rna( silu(A@Bg) * (A@Bu) )
// One launch: blockIdx.z in [0..7]; z<7 routed expert (gathered rows, hr out),
// z==7 shared expert (all tokens, hs out). All operands pre-rounded: NO cvt.
// Tile 128x64, BK=32, 2-stage cp.async. 8 warps 4x2, warp tile 32x32.
// ---------------------------------------------------------------------------
#define H_BK 32
#define H_AP 36
#define H_BP 68
#define H_ASZ (128 * H_AP)
#define H_BSZ (H_BK * H_BP)
#define H_STG (H_ASZ + 2 * H_BSZ)

__global__ __launch_bounds__(NTHREADS, 2)
void hidden_kernel(const float* __restrict__ A,
                   const float* __restrict__ Wg,   // routed stack [7,K,N] rounded
                   const float* __restrict__ Wu,
                   const float* __restrict__ Wsg,  // shared [K,N] rounded
                   const float* __restrict__ Wsu,
                   float* __restrict__ Hr,
                   float* __restrict__ Hs) {
    extern __shared__ __align__(16) float smem[];
    const int K = DIMK, N = HIDN;

    int z = blockIdx.z;
    bool routed = (z < NEXP);
    int off, count;
    const float *BgP, *BuP;
    float* H;
    if (routed) {
        off = g_off[z]; count = g_off[z + 1] - off;
        BgP = Wg + (size_t)z * K * N;
        BuP = Wu + (size_t)z * K * N;
        H = Hr;
    } else {
        off = 0; count = TOK;
        BgP = Wsg; BuP = Wsu;
        H = Hs;
    }
    int m0 = blockIdx.x * BM;
    if (m0 >= count) return;
    int n0 = blockIdx.y * 64;

    int tid  = threadIdx.x;
    int warp = tid >> 5;
    int wm   = warp >> 1;
    int wn   = warp & 1;

    int arow[4];
#pragma unroll
    for (int c = 0; c < 4; c++) {
        int lin = tid + c * NTHREADS;
        int r = lin >> 3;
        int rr = m0 + r;
        if (rr >= count) rr = m0;
        arow[c] = routed ? g_perm[off + rr] : rr;
    }

    auto load_stage = [&](int kt, int s) {
        float* As = smem + s * H_STG;
        float* Bs = As + H_ASZ;
#pragma unroll
        for (int c = 0; c < 4; c++) {
            int lin = tid + c * NTHREADS;
            int r   = lin >> 3;
            int kc  = (lin & 7) * 4;
            cp_async16(&As[r * H_AP + kc], A + (size_t)arow[c] * K + kt + kc);
        }
#pragma unroll
        for (int c = 0; c < 4; c++) {
            int lin = tid + c * NTHREADS;
            int t2  = lin >> 9;
            int w   = lin & 511;
            int br  = w >> 4;
            int bc  = (w & 15) * 4;
            const float* src = (t2 == 0 ? BgP : BuP) + (size_t)(kt + br) * N + n0 + bc;
            cp_async16(&Bs[t2 * H_BSZ + br * H_BP + bc], src);
        }
    };

    wmma::fragment<wmma::accumulator, 16, 16, 8, float> accg[2][2], accu[2][2];
#pragma unroll
    for (int i = 0; i < 2; i++)
#pragma unroll
        for (int j = 0; j < 2; j++) {
            wmma::fill_fragment(accg[i][j], 0.0f);
            wmma::fill_fragment(accu[i][j], 0.0f);
        }

    const int nk = K / H_BK;
    load_stage(0, 0);
    cp_commit();

    for (int kt = 0; kt < nk; kt++) {
        if (kt + 1 < nk) {
            load_stage((kt + 1) * H_BK, (kt + 1) & 1);
            cp_commit();
            cp_wait<1>();
        } else {
            cp_wait<0>();
        }
        __syncthreads();

        float* As = smem + (kt & 1) * H_STG;
        float* Bs = As + H_ASZ;

#pragma unroll
        for (int k0 = 0; k0 < H_BK; k0 += 8) {
            wmma::fragment<wmma::matrix_a, 16, 16, 8, wmma::precision::tf32,
                           wmma::row_major> a[2];
            wmma::fragment<wmma::matrix_b, 16, 16, 8, wmma::precision::tf32,
                           wmma::row_major> bg[2], bu[2];
#pragma unroll
            for (int i = 0; i < 2; i++)
                wmma::load_matrix_sync(a[i], &As[(wm * 32 + i * 16) * H_AP + k0], H_AP);
#pragma unroll
            for (int j = 0; j < 2; j++) {
                wmma::load_matrix_sync(bg[j], &Bs[0 * H_BSZ + k0 * H_BP + wn * 32 + j * 16], H_BP);
                wmma::load_matrix_sync(bu[j], &Bs[1 * H_BSZ + k0 * H_BP + wn * 32 + j * 16], H_BP);
            }
            // operands pre-rounded to tf32: no cvt needed
#pragma unroll
            for (int i = 0; i < 2; i++)
#pragma unroll
                for (int j = 0; j < 2; j++) {
                    wmma::mma_sync(accg[i][j], a[i], bg[j], accg[i][j]);
                    wmma::mma_sync(accu[i][j], a[i], bu[j], accu[i][j]);
                }
        }
        __syncthreads();
    }

    // epilogue: h = rna(silu(g) * u) — pre-rounds A for the down GEMM
#pragma unroll
    for (int i = 0; i < 2; i++)
#pragma unroll
        for (int j = 0; j < 2; j++)
#pragma unroll
            for (int t = 0; t < accg[i][j].num_elements; t++)
                accg[i][j].x[t] = rna_tf32(silu_f(accg[i][j].x[t]) * accu[i][j].x[t]);

    if (m0 + BM <= count) {
#pragma unroll
        for (int i = 0; i < 2; i++)
#pragma unroll
            for (int j = 0; j < 2; j++)
                wmma::store_matrix_sync(
                    H + (size_t)(off + m0 + wm * 32 + i * 16) * N + n0 + wn * 32 + j * 16,
                    accg[i][j], N, wmma::mem_row_major);
    } else {
        __syncthreads();
        float* Cs = smem;
#pragma unroll
        for (int i = 0; i < 2; i++)
#pragma unroll
            for (int j = 0; j < 2; j++)
                wmma::store_matrix_sync(&Cs[(wm * 32 + i * 16) * 68 + wn * 32 + j * 16],
                                        accg[i][j], 68, wmma::mem_row_major);
        __syncthreads();
        for (int lin = tid; lin < 128 * 64; lin += NTHREADS) {
            int r  = lin >> 6;
            int cc = lin & 63;
            if (m0 + r >= count) continue;
            H[(size_t)(off + m0 + r) * N + n0 + cc] = Cs[r * 68 + cc];
        }
    }
}

// ---------------------------------------------------------------------------
// Down-projection: C-tile 128x128, BK=32, 2-stage. warps 2x4, warp 64x32.
// EPI 2: plain write (shared). EPI 3: scatter + scale-add (routed).
// No cvt (A=h pre-rounded at hidden epilogue; B pre-rounded in prep).
// ---------------------------------------------------------------------------
#define D_BK 32
#define D_AP 36
#define D_BP 132
#define D_ASZ (128 * D_AP)
#define D_BSZ (D_BK * D_BP)
#define D_STG (D_ASZ + D_BSZ)

template <int EPI, bool GROUPED>
__global__ __launch_bounds__(NTHREADS, 2)
void down_kernel(const float* __restrict__ A,
                 const float* __restrict__ Bw,
                 float* __restrict__ C,
                 int M_dense, long long b_stride) {
    extern __shared__ __align__(16) float smem[];
    const int K = HIDN, N = DIMK;

    int e, off, count;
    if (GROUPED) { e = blockIdx.z; off = g_off[e]; count = g_off[e + 1] - off; }
    else         { e = 0; off = 0; count = M_dense; }
    int m0 = blockIdx.x * BM;
    if (m0 >= count) return;
    int n0 = blockIdx.y * 128;

    const float* Bp = Bw + (size_t)e * (size_t)b_stride;

    int tid  = threadIdx.x;
    int warp = tid >> 5;
    int wm   = warp >> 2;
    int wn   = warp & 3;

    int arow[4];
#pragma unroll
    for (int c = 0; c < 4; c++) {
        int lin = tid + c * NTHREADS;
        int r = lin >> 3;
        int rr = m0 + r;
        if (rr >= count) rr = m0;
        arow[c] = off + rr;
    }

    auto load_stage = [&](int kt, int s) {
        float* As = smem + s * D_STG;
        float* Bs = As + D_ASZ;
#pragma unroll
        for (int c = 0; c < 4; c++) {
            int lin = tid + c * NTHREADS;
            int r   = lin >> 3;
            int kc  = (lin & 7) * 4;
            cp_async16(&As[r * D_AP + kc], A + (size_t)arow[c] * K + kt + kc);
        }
#pragma unroll
        for (int c = 0; c < 4; c++) {
            int lin = tid + c * NTHREADS;
            int br  = lin >> 5;
            int bc  = (lin & 31) * 4;
            cp_async16(&Bs[br * D_BP + bc], Bp + (size_t)(kt + br) * N + n0 + bc);
        }
    };

    wmma::fragment<wmma::accumulator, 16, 16, 8, float> acc[4][2];
#pragma unroll
    for (int i = 0; i < 4; i++)
#pragma unroll
        for (int j = 0; j < 2; j++)
            wmma::fill_fragment(acc[i][j], 0.0f);

    const int nk = K / D_BK;
    load_stage(0, 0);
    cp_commit();

    for (int kt = 0; kt < nk; kt++) {
        if (kt + 1 < nk) {
            load_stage((kt + 1) * D_BK, (kt + 1) & 1);
            cp_commit();
            cp_wait<1>();
        } else {
            cp_wait<0>();
        }
        __syncthreads();

        float* As = smem + (kt & 1) * D_STG;
        float* Bs = As + D_ASZ;

#pragma unroll
        for (int k0 = 0; k0 < D_BK; k0 += 8) {
            wmma::fragment<wmma::matrix_a, 16, 16, 8, wmma::precision::tf32,
                           wmma::row_major> a[4];
            wmma::fragment<wmma::matrix_b, 16, 16, 8, wmma::precision::tf32,
                           wmma::row_major> b[2];
#pragma unroll
            for (int i = 0; i < 4; i++)
                wmma::load_matrix_sync(a[i], &As[(wm * 64 + i * 16) * D_AP + k0], D_AP);
#pragma unroll
            for (int j = 0; j < 2; j++)
                wmma::load_matrix_sync(b[j], &Bs[k0 * D_BP + wn * 32 + j * 16], D_BP);
#pragma unroll
            for (int i = 0; i < 4; i++)
#pragma unroll
                for (int j = 0; j < 2; j++)
                    wmma::mma_sync(acc[i][j], a[i], b[j], acc[i][j]);
        }
        __syncthreads();
    }

    if (EPI == 2) {
#pragma unroll
        for (int i = 0; i < 4; i++)
#pragma unroll
            for (int j = 0; j < 2; j++)
                wmma::store_matrix_sync(
                    C + (size_t)(m0 + wm * 64 + i * 16) * N + n0 + wn * 32 + j * 16,
                    acc[i][j], N, wmma::mem_row_major);
    } else {
        __syncthreads();
        float* Cs = smem;
#pragma unroll
        for (int i = 0; i < 4; i++)
#pragma unroll
            for (int j = 0; j < 2; j++)
                wmma::store_matrix_sync(&Cs[(wm * 64 + i * 16) * D_BP + wn * 32 + j * 16],
                                        acc[i][j], D_BP, wmma::mem_row_major);
        __syncthreads();
        for (int lin = tid; lin < 128 * 128; lin += NTHREADS) {
            int r  = lin >> 7;
            int cc = lin & 127;
            if (m0 + r >= count) continue;
            int tok = g_perm[off + m0 + r];
            size_t a = (size_t)tok * N + n0 + cc;
            C[a] += g_scale[tok] * Cs[r * D_BP + cc];
        }
    }
}

// ---------------------------------------------------------------------------
// Launch
// ---------------------------------------------------------------------------
extern "C" void kernel_launch(void* const* d_in, const int* in_sizes, int n_in,
                              void* d_out, int out_size) {
    const float* x        = (const float*)d_in[0];
    const float* w_router = (const float*)d_in[1];
    const float* w_up     = (const float*)d_in[2];
    const float* w_gate   = (const float*)d_in[3];
    const float* w_down   = (const float*)d_in[4];
    const float* ws_up    = (const float*)d_in[5];
    const float* ws_gate  = (const float*)d_in[6];
    const float* ws_down  = (const float*)d_in[7];
    float* out = (float*)d_out;

    void* p;
    cudaGetSymbolAddress(&p, g_xr);   float* xr   = (float*)p;
    cudaGetSymbolAddress(&p, g_hr);   float* hr   = (float*)p;
    cudaGetSymbolAddress(&p, g_hs);   float* hs   = (float*)p;
    cudaGetSymbolAddress(&p, g_wgt);  float* wgt  = (float*)p;
    cudaGetSymbolAddress(&p, g_wut);  float* wut  = (float*)p;
    cudaGetSymbolAddress(&p, g_wdt);  float* wdt  = (float*)p;
    cudaGetSymbolAddress(&p, g_wsgt); float* wsgt = (float*)p;
    cudaGetSymbolAddress(&p, g_wsut); float* wsut = (float*)p;
    cudaGetSymbolAddress(&p, g_wsdt); float* wsdt = (float*)p;

    const int h_smem = 2 * H_STG * (int)sizeof(float);
    const int d_smem = 2 * D_STG * (int)sizeof(float);
    cudaFuncSetAttribute(hidden_kernel,
                         cudaFuncAttributeMaxDynamicSharedMemorySize, h_smem);
    cudaFuncSetAttribute(down_kernel<2, false>,
                         cudaFuncAttributeMaxDynamicSharedMemorySize, d_smem);
    cudaFuncSetAttribute(down_kernel<3, true >,
                         cudaFuncAttributeMaxDynamicSharedMemorySize, d_smem);

    router_kernel<<<TOK / 8, 256>>>(x, w_router);
    plan_kernel<<<1, 256>>>();

    // prep: RNA-round activations + all weights (removes all in-loop cvt)
    {
        const int T = 256;
        int n4;
        n4 = TOK * DIMK / 4;
        round4_kernel<<<(n4 + T - 1) / T, T>>>((const float4*)x, (float4*)xr, n4);
        n4 = NEXP * DIMK * HIDN / 4;
        round4_kernel<<<(n4 + T - 1) / T, T>>>((const float4*)w_gate, (float4*)wgt, n4);
        round4_kernel<<<(n4 + T - 1) / T, T>>>((const float4*)w_up,   (float4*)wut, n4);
        round4_kernel<<<(n4 + T - 1) / T, T>>>((const float4*)w_down, (float4*)wdt, n4);
        n4 = DIMK * HIDN / 4;
        round4_kernel<<<(n4 + T - 1) / T, T>>>((const float4*)ws_gate, (float4*)wsgt, n4);
        round4_kernel<<<(n4 + T - 1) / T, T>>>((const float4*)ws_up,   (float4*)wsut, n4);
        round4_kernel<<<(n4 + T - 1) / T, T>>>((const float4*)ws_down, (float4*)wsdt, n4);
    }

    const long long dn_stride = (long long)HIDN * DIMK;

    // fused hidden: z<7 routed experts, z==7 shared
    dim3 grH(TOK / BM, HIDN / 64, NE_ALL);
    hidden_kernel<<<grH, NTHREADS, h_smem>>>(xr, wgt, wut, wsgt, wsut, hr, hs);

    // shared down writes out densely, then routed down adds
    dim3 grD_s(TOK / BM, DIMK / 128, 1);
    dim3 grD_r(TOK / BM, DIMK / 128, NEXP);
    down_kernel<2, false><<<grD_s, NTHREADS, d_smem>>>(hs, wsdt, out, TOK, 0);
    down_kernel<3, true ><<<grD_r, NTHREADS, d_smem>>>(hr, wdt, out, 0, dn_stride);
}

// round 6
// speedup vs baseline: 1.3151x; 1.3151x over previous
#include <cuda_runtime.h>
#include <mma.h>
#include <math.h>
#include <stdint.h>

using namespace nvcuda;

#define TOK   2048
#define DIMK  1024
#define HIDN  4096
#define NEXP  7
#define NE_ALL 8
#define ALPHA_C 2.0f
#define NTHREADS 256

// ---------------------------------------------------------------------------
// Scratch
// ---------------------------------------------------------------------------
__device__ int   g_eidx[TOK];
__device__ float g_scale[TOK];
__device__ int   g_perm[TOK];
__device__ int   g_off[NEXP + 1];
__device__ __align__(128) float g_xr[(size_t)TOK * DIMK];
__device__ __align__(128) float g_hr[(size_t)TOK * HIDN];   // routed hidden (perm rows)
__device__ __align__(128) float g_hs[(size_t)TOK * HIDN];   // shared hidden (token rows)

// ---------------------------------------------------------------------------
// helpers
// ---------------------------------------------------------------------------
__device__ __forceinline__ float rna_tf32(float x) {
    float r; asm("cvt.rna.tf32.f32 %0, %1;" : "=f"(r) : "f"(x)); return r;
}
__device__ __forceinline__ void cp_async16(void* smem_dst, const void* gmem_src) {
    uint32_t s = (uint32_t)__cvta_generic_to_shared(smem_dst);
    asm volatile("cp.async.cg.shared.global [%0], [%1], 16;\n" :: "r"(s), "l"(gmem_src));
}
__device__ __forceinline__ void cp_commit() { asm volatile("cp.async.commit_group;\n"); }
template <int N> __device__ __forceinline__ void cp_wait() {
    asm volatile("cp.async.wait_group %0;\n" :: "n"(N));
}
__device__ __forceinline__ float silu_f(float v) { return v / (1.0f + expf(-v)); }

__global__ void round4_kernel(const float4* __restrict__ s, float4* __restrict__ d, int n4) {
    int i = blockIdx.x * blockDim.x + threadIdx.x;
    if (i >= n4) return;
    float4 v = s[i];
    v.x = rna_tf32(v.x); v.y = rna_tf32(v.y);
    v.z = rna_tf32(v.z); v.w = rna_tf32(v.w);
    d[i] = v;
}
__global__ void zero4_kernel(float4* __restrict__ d, int n4) {
    int i = blockIdx.x * blockDim.x + threadIdx.x;
    if (i < n4) d[i] = make_float4(0.f, 0.f, 0.f, 0.f);
}

// ---------------------------------------------------------------------------
// Router (fp32 exact) + plan
// ---------------------------------------------------------------------------
__global__ void router_kernel(const float* __restrict__ x, const float* __restrict__ wr) {
    int gw   = (blockIdx.x * blockDim.x + threadIdx.x) >> 5;
    int lane = threadIdx.x & 31;
    if (gw >= TOK) return;
    const float* xr = x + (size_t)gw * DIMK;
    float acc[NE_ALL];
#pragma unroll
    for (int e = 0; e < NE_ALL; e++) acc[e] = 0.f;
    for (int d = lane; d < DIMK; d += 32) {
        float xv = xr[d];
        const float4* w4 = reinterpret_cast<const float4*>(wr + (size_t)d * NE_ALL);
        float4 w0 = w4[0], w1 = w4[1];
        acc[0] += xv * w0.x; acc[1] += xv * w0.y;
        acc[2] += xv * w0.z; acc[3] += xv * w0.w;
        acc[4] += xv * w1.x; acc[5] += xv * w1.y;
        acc[6] += xv * w1.z; acc[7] += xv * w1.w;
    }
#pragma unroll
    for (int e = 0; e < NE_ALL; e++)
#pragma unroll
        for (int o = 16; o > 0; o >>= 1)
            acc[e] += __shfl_xor_sync(0xffffffffu, acc[e], o);
    if (lane == 0) {
        float m = acc[0]; int idx = 0;
#pragma unroll
        for (int e = 1; e < NE_ALL; e++)
            if (acc[e] > m) { m = acc[e]; idx = e; }
        float s = 0.f;
#pragma unroll
        for (int e = 0; e < NE_ALL; e++) s += expf(acc[e] - m);
        g_scale[gw] = ALPHA_C / s;
        g_eidx[gw]  = idx;
    }
}
__global__ void plan_kernel() {
    __shared__ int cnt[NEXP], offs[NEXP + 1], cur[NEXP];
    int tid = threadIdx.x;
    if (tid < NEXP) cnt[tid] = 0;
    __syncthreads();
    for (int t = tid; t < TOK; t += blockDim.x) {
        int e = g_eidx[t];
        if (e < NEXP) atomicAdd(&cnt[e], 1);
    }
    __syncthreads();
    if (tid == 0) {
        int o = 0;
        for (int e = 0; e < NEXP; e++) { offs[e] = o; cur[e] = o; o += cnt[e]; }
        offs[NEXP] = o;
    }
    __syncthreads();
    for (int t = tid; t < TOK; t += blockDim.x) {
        int e = g_eidx[t];
        if (e < NEXP) g_perm[atomicAdd(&cur[e], 1)] = t;
    }
    if (tid <= NEXP) g_off[tid] = offs[tid];
}

// ---------------------------------------------------------------------------
// Hidden: H = rna( silu(A@Wg) * (A@Wu) )
// z<7: routed expert (gathered A rows -> Hr perm-rows); z==7: shared -> Hs.
// Block 128x128, dual B, BK=32, 3-stage cp.async. 8 warps 2x4, warp 64x32x2.
// A (=x rounded / h) pre-rounded; B (weights) cvt'd per-fragment in loop.
// ---------------------------------------------------------------------------
#define H_AP 36
#define H_BP 132
#define H_ASZ (128 * H_AP)            // 4608 floats
#define H_BSZ (32 * H_BP)             // 4224 floats
#define H_STG (H_ASZ + 2 * H_BSZ)     // 13056 floats = 52224 B

__global__ __launch_bounds__(NTHREADS, 1)
void hidden_kernel(const float* __restrict__ A,
                   const float* __restrict__ Wg,   // [7,K,N] raw
                   const float* __restrict__ Wu,
                   const float* __restrict__ Wsg,  // [K,N] raw
                   const float* __restrict__ Wsu,
                   float* __restrict__ Hr,
                   float* __restrict__ Hs) {
    extern __shared__ __align__(16) float smem[];
    const int K = DIMK, N = HIDN;

    int z = blockIdx.z;
    bool routed = (z < NEXP);
    int off, count;
    const float *BgP, *BuP;
    float* H;
    if (routed) {
        off = g_off[z]; count = g_off[z + 1] - off;
        BgP = Wg + (size_t)z * K * N;
        BuP = Wu + (size_t)z * K * N;
        H = Hr;
    } else {
        off = 0; count = TOK;
        BgP = Wsg; BuP = Wsu;
        H = Hs;
    }
    int m0 = blockIdx.x * 128;
    if (m0 >= count) return;
    int n0 = blockIdx.y * 128;

    int tid  = threadIdx.x;
    int warp = tid >> 5;
    int wm   = warp >> 2;   // 0..1  (64-row band)
    int wn   = warp & 3;    // 0..3  (32-col band)

    int arow[4];
#pragma unroll
    for (int c = 0; c < 4; c++) {
        int r = (tid + c * NTHREADS) >> 3;
        int rr = m0 + r;
        if (rr >= count) rr = count - 1;
        arow[c] = routed ? g_perm[off + rr] : rr;
    }

    auto load_stage = [&](int kt, int s) {
        float* As = smem + s * H_STG;
        float* Bg = As + H_ASZ;
        float* Bu = Bg + H_BSZ;
#pragma unroll
        for (int c = 0; c < 4; c++) {
            int lin = tid + c * NTHREADS;
            int r   = lin >> 3;
            int kc  = (lin & 7) * 4;
            cp_async16(&As[r * H_AP + kc], A + (size_t)arow[c] * K + kt * 32 + kc);
        }
#pragma unroll
        for (int c = 0; c < 4; c++) {
            int lin = tid + c * NTHREADS;
            int br  = lin >> 5;
            int bc  = (lin & 31) * 4;
            size_t src = (size_t)(kt * 32 + br) * N + n0 + bc;
            cp_async16(&Bg[br * H_BP + bc], BgP + src);
            cp_async16(&Bu[br * H_BP + bc], BuP + src);
        }
        cp_commit();
    };

    wmma::fragment<wmma::accumulator, 16, 16, 8, float> accg[4][2], accu[4][2];
#pragma unroll
    for (int i = 0; i < 4; i++)
#pragma unroll
        for (int j = 0; j < 2; j++) {
            wmma::fill_fragment(accg[i][j], 0.0f);
            wmma::fill_fragment(accu[i][j], 0.0f);
        }

    const int nk = K / 32;   // 32
    load_stage(0, 0);
    load_stage(1, 1);

    for (int kt = 0; kt < nk; kt++) {
        if (kt + 1 < nk) cp_wait<1>(); else cp_wait<0>();
        __syncthreads();

        float* As = smem + (kt % 3) * H_STG;
        float* Bg = As + H_ASZ;
        float* Bu = Bg + H_BSZ;

#pragma unroll
        for (int k0 = 0; k0 < 32; k0 += 8) {
            wmma::fragment<wmma::matrix_a, 16, 16, 8, wmma::precision::tf32,
                           wmma::row_major> a[4];
            wmma::fragment<wmma::matrix_b, 16, 16, 8, wmma::precision::tf32,
                           wmma::row_major> bg[2], bu[2];
#pragma unroll
            for (int i = 0; i < 4; i++)
                wmma::load_matrix_sync(a[i], &As[(wm * 64 + i * 16) * H_AP + k0], H_AP);
#pragma unroll
            for (int j = 0; j < 2; j++) {
                wmma::load_matrix_sync(bg[j], &Bg[k0 * H_BP + wn * 32 + j * 16], H_BP);
                wmma::load_matrix_sync(bu[j], &Bu[k0 * H_BP + wn * 32 + j * 16], H_BP);
#pragma unroll
                for (int t = 0; t < bg[j].num_elements; t++) {
                    bg[j].x[t] = wmma::__float_to_tf32(bg[j].x[t]);
                    bu[j].x[t] = wmma::__float_to_tf32(bu[j].x[t]);
                }
            }
#pragma unroll
            for (int i = 0; i < 4; i++)
#pragma unroll
                for (int j = 0; j < 2; j++) {
                    wmma::mma_sync(accg[i][j], a[i], bg[j], accg[i][j]);
                    wmma::mma_sync(accu[i][j], a[i], bu[j], accu[i][j]);
                }
        }
        if (kt + 2 < nk) load_stage(kt + 2, (kt + 2) % 3);
    }

    // h = rna(silu(g)*u)  (pre-rounds A for the down GEMM)
#pragma unroll
    for (int i = 0; i < 4; i++)
#pragma unroll
        for (int j = 0; j < 2; j++)
#pragma unroll
            for (int t = 0; t < accg[i][j].num_elements; t++)
                accg[i][j].x[t] = rna_tf32(silu_f(accg[i][j].x[t]) * accu[i][j].x[t]);

    if (m0 + 128 <= count) {
#pragma unroll
        for (int i = 0; i < 4; i++)
#pragma unroll
            for (int j = 0; j < 2; j++)
                wmma::store_matrix_sync(
                    H + (size_t)(off + m0 + wm * 64 + i * 16) * N + n0 + wn * 32 + j * 16,
                    accg[i][j], N, wmma::mem_row_major);
    } else {
        __syncthreads();
        float* Cs = smem;   // 128 x 132 staging
#pragma unroll
        for (int i = 0; i < 4; i++)
#pragma unroll
            for (int j = 0; j < 2; j++)
                wmma::store_matrix_sync(&Cs[(wm * 64 + i * 16) * 132 + wn * 32 + j * 16],
                                        accg[i][j], 132, wmma::mem_row_major);
        __syncthreads();
        for (int lin = tid; lin < 128 * 128; lin += NTHREADS) {
            int r  = lin >> 7;
            int cc = lin & 127;
            if (m0 + r >= count) continue;
            H[(size_t)(off + m0 + r) * N + n0 + cc] = Cs[r * 132 + cc];
        }
    }
}

// ---------------------------------------------------------------------------
// Down (fused shared+routed): out += contributions via atomicAdd (out zeroed).
// z<7 routed (A=hr perm rows, scale per token), z==7 shared (A=hs).
// Block 128x128, BK=32, 3 stages, 8 warps 2x4, warp 64x32. 2 CTAs/SM.
// ---------------------------------------------------------------------------
#define D_AP 36
#define D_BP 132
#define D_ASZ (128 * D_AP)
#define D_BSZ (32 * D_BP)
#define D_STG (D_ASZ + D_BSZ)   // 8832 floats = 35328 B

__global__ __launch_bounds__(NTHREADS, 2)
void down_kernel(const float* __restrict__ Hr,
                 const float* __restrict__ Hs,
                 const float* __restrict__ Wd,   // [7,K,N] raw
                 const float* __restrict__ Wsd,  // [K,N] raw
                 float* __restrict__ out) {
    extern __shared__ __align__(16) float smem[];
    const int K = HIDN, N = DIMK;

    int z = blockIdx.z;
    bool routed = (z < NEXP);
    int off, count;
    const float *Ap, *Bp;
    if (routed) {
        off = g_off[z]; count = g_off[z + 1] - off;
        Ap = Hr; Bp = Wd + (size_t)z * K * N;
    } else {
        off = 0; count = TOK;
        Ap = Hs; Bp = Wsd;
    }
    int m0 = blockIdx.x * 128;
    if (m0 >= count) return;
    int n0 = blockIdx.y * 128;

    int tid  = threadIdx.x;
    int warp = tid >> 5;
    int wm   = warp >> 2;
    int wn   = warp & 3;

    int arow[4];
#pragma unroll
    for (int c = 0; c < 4; c++) {
        int r = (tid + c * NTHREADS) >> 3;
        int rr = m0 + r;
        if (rr >= count) rr = count - 1;
        arow[c] = off + rr;
    }

    auto load_stage = [&](int kt, int s) {
        float* As = smem + s * D_STG;
        float* Bs = As + D_ASZ;
#pragma unroll
        for (int c = 0; c < 4; c++) {
            int lin = tid + c * NTHREADS;
            int r   = lin >> 3;
            int kc  = (lin & 7) * 4;
            cp_async16(&As[r * D_AP + kc], Ap + (size_t)arow[c] * K + kt * 32 + kc);
        }
#pragma unroll
        for (int c = 0; c < 4; c++) {
            int lin = tid + c * NTHREADS;
            int br  = lin >> 5;
            int bc  = (lin & 31) * 4;
            cp_async16(&Bs[br * D_BP + bc], Bp + (size_t)(kt * 32 + br) * N + n0 + bc);
        }
        cp_commit();
    };

    wmma::fragment<wmma::accumulator, 16, 16, 8, float> acc[4][2];
#pragma unroll
    for (int i = 0; i < 4; i++)
#pragma unroll
        for (int j = 0; j < 2; j++)
            wmma::fill_fragment(acc[i][j], 0.0f);

    const int nk = K / 32;   // 128
    load_stage(0, 0);
    load_stage(1, 1);

    for (int kt = 0; kt < nk; kt++) {
        if (kt + 1 < nk) cp_wait<1>(); else cp_wait<0>();
        __syncthreads();

        float* As = smem + (kt % 3) * D_STG;
        float* Bs = As + D_ASZ;

#pragma unroll
        for (int k0 = 0; k0 < 32; k0 += 8) {
            wmma::fragment<wmma::matrix_a, 16, 16, 8, wmma::precision::tf32,
                           wmma::row_major> a[4];
            wmma::fragment<wmma::matrix_b, 16, 16, 8, wmma::precision::tf32,
                           wmma::row_major> b[2];
#pragma unroll
            for (int i = 0; i < 4; i++)
                wmma::load_matrix_sync(a[i], &As[(wm * 64 + i * 16) * D_AP + k0], D_AP);
#pragma unroll
            for (int j = 0; j < 2; j++) {
                wmma::load_matrix_sync(b[j], &Bs[k0 * D_BP + wn * 32 + j * 16], D_BP);
#pragma unroll
                for (int t = 0; t < b[j].num_elements; t++)
                    b[j].x[t] = wmma::__float_to_tf32(b[j].x[t]);
            }
#pragma unroll
            for (int i = 0; i < 4; i++)
#pragma unroll
                for (int j = 0; j < 2; j++)
                    wmma::mma_sync(acc[i][j], a[i], b[j], acc[i][j]);
        }
        if (kt + 2 < nk) load_stage(kt + 2, (kt + 2) % 3);
    }

    // epilogue: stage -> atomicAdd into out
    __syncthreads();
    float* Cs = smem;   // 128 x 132
#pragma unroll
    for (int i = 0; i < 4; i++)
#pragma unroll
        for (int j = 0; j < 2; j++)
            wmma::store_matrix_sync(&Cs[(wm * 64 + i * 16) * 132 + wn * 32 + j * 16],
                                    acc[i][j], 132, wmma::mem_row_major);
    __syncthreads();
    for (int lin = tid; lin < 128 * 128; lin += NTHREADS) {
        int r  = lin >> 7;
        int cc = lin & 127;
        if (m0 + r >= count) continue;
        float v = Cs[r * 132 + cc];
        int tok;
        if (routed) {
            tok = g_perm[off + m0 + r];
            v *= g_scale[tok];
        } else {
            tok = m0 + r;
        }
        atomicAdd(&out[(size_t)tok * N + n0 + cc], v);
    }
}

// ---------------------------------------------------------------------------
// Launch
// ---------------------------------------------------------------------------
extern "C" void kernel_launch(void* const* d_in, const int* in_sizes, int n_in,
                              void* d_out, int out_size) {
    const float* x        = (const float*)d_in[0];
    const float* w_router = (const float*)d_in[1];
    const float* w_up     = (const float*)d_in[2];
    const float* w_gate   = (const float*)d_in[3];
    const float* w_down   = (const float*)d_in[4];
    const float* ws_up    = (const float*)d_in[5];
    const float* ws_gate  = (const float*)d_in[6];
    const float* ws_down  = (const float*)d_in[7];
    float* out = (float*)d_out;

    void* p;
    cudaGetSymbolAddress(&p, g_xr); float* xr = (float*)p;
    cudaGetSymbolAddress(&p, g_hr); float* hr = (float*)p;
    cudaGetSymbolAddress(&p, g_hs); float* hs = (float*)p;

    const int h_smem = 3 * H_STG * (int)sizeof(float);   // 156672
    const int d_smem = 3 * D_STG * (int)sizeof(float);   // 105984
    cudaFuncSetAttribute(hidden_kernel, cudaFuncAttributeMaxDynamicSharedMemorySize, h_smem);
    cudaFuncSetAttribute(down_kernel,   cudaFuncAttributeMaxDynamicSharedMemorySize, d_smem);

    router_kernel<<<TOK / 8, 256>>>(x, w_router);
    plan_kernel<<<1, 256>>>();
    round4_kernel<<<TOK * DIMK / 4 / 256, 256>>>((const float4*)x, (float4*)xr,
                                                 TOK * DIMK / 4);
    zero4_kernel<<<TOK * DIMK / 4 / 256, 256>>>((float4*)out, TOK * DIMK / 4);

    dim3 grH(TOK / 128, HIDN / 128, NE_ALL);   // 16 x 32 x 8
    hidden_kernel<<<grH, NTHREADS, h_smem>>>(xr, w_gate, w_up, ws_gate, ws_up, hr, hs);

    dim3 grD(TOK / 128, DIMK / 128, NE_ALL);   // 16 x 8 x 8
    down_kernel<<<grD, NTHREADS, d_smem>>>(hr, hs, w_down, ws_down, out);
}

// round 7
// speedup vs baseline: 3.8378x; 2.9182x over previous
#include <cuda_runtime.h>
#include <cuda_fp16.h>
#include <mma.h>
#include <math.h>
#include <stdint.h>

using namespace nvcuda;

#define TOK   2048
#define DIMK  1024
#define HIDN  4096
#define NEXP  7
#define NE_ALL 8
#define ALPHA_C 2.0f
#define NTHREADS 256

// ---------------------------------------------------------------------------
// Scratch
// ---------------------------------------------------------------------------
__device__ int   g_eidx[TOK];
__device__ float g_scale[TOK];
__device__ int   g_perm[TOK];
__device__ int   g_off[NEXP + 1];
__device__ __align__(128) __half g_xh[(size_t)TOK * DIMK];
__device__ __align__(128) __half g_hrh[(size_t)TOK * HIDN];   // routed hidden (perm rows)
__device__ __align__(128) __half g_hsh[(size_t)TOK * HIDN];   // shared hidden
// fp16 weight copies
__device__ __align__(128) __half g_wgh[(size_t)NEXP * DIMK * HIDN];
__device__ __align__(128) __half g_wuh[(size_t)NEXP * DIMK * HIDN];
__device__ __align__(128) __half g_wdh[(size_t)NEXP * HIDN * DIMK];
__device__ __align__(128) __half g_wsgh[(size_t)DIMK * HIDN];
__device__ __align__(128) __half g_wsuh[(size_t)DIMK * HIDN];
__device__ __align__(128) __half g_wsdh[(size_t)HIDN * DIMK];

// ---------------------------------------------------------------------------
// helpers
// ---------------------------------------------------------------------------
__device__ __forceinline__ void cp_async16(void* smem_dst, const void* gmem_src) {
    uint32_t s = (uint32_t)__cvta_generic_to_shared(smem_dst);
    asm volatile("cp.async.cg.shared.global [%0], [%1], 16;\n" :: "r"(s), "l"(gmem_src));
}
__device__ __forceinline__ void cp_commit() { asm volatile("cp.async.commit_group;\n"); }
template <int N> __device__ __forceinline__ void cp_wait() {
    asm volatile("cp.async.wait_group %0;\n" :: "n"(N));
}
__device__ __forceinline__ float silu_f(float v) { return v / (1.0f + expf(-v)); }

// fp32 -> fp16 conversion, 8 elems/thread
__global__ void f2h_kernel(const float4* __restrict__ s, uint4* __restrict__ d, int n8) {
    int i = blockIdx.x * blockDim.x + threadIdx.x;
    if (i >= n8) return;
    float4 v0 = s[2 * i], v1 = s[2 * i + 1];
    __half2 h0 = __floats2half2_rn(v0.x, v0.y);
    __half2 h1 = __floats2half2_rn(v0.z, v0.w);
    __half2 h2 = __floats2half2_rn(v1.x, v1.y);
    __half2 h3 = __floats2half2_rn(v1.z, v1.w);
    uint4 o;
    o.x = *reinterpret_cast<unsigned*>(&h0);
    o.y = *reinterpret_cast<unsigned*>(&h1);
    o.z = *reinterpret_cast<unsigned*>(&h2);
    o.w = *reinterpret_cast<unsigned*>(&h3);
    d[i] = o;
}
__global__ void zero4_kernel(float4* __restrict__ d, int n4) {
    int i = blockIdx.x * blockDim.x + threadIdx.x;
    if (i < n4) d[i] = make_float4(0.f, 0.f, 0.f, 0.f);
}

// ---------------------------------------------------------------------------
// Router (fp32 exact) + plan
// ---------------------------------------------------------------------------
__global__ void router_kernel(const float* __restrict__ x, const float* __restrict__ wr) {
    int gw   = (blockIdx.x * blockDim.x + threadIdx.x) >> 5;
    int lane = threadIdx.x & 31;
    if (gw >= TOK) return;
    const float* xr = x + (size_t)gw * DIMK;
    float acc[NE_ALL];
#pragma unroll
    for (int e = 0; e < NE_ALL; e++) acc[e] = 0.f;
    for (int d = lane; d < DIMK; d += 32) {
        float xv = xr[d];
        const float4* w4 = reinterpret_cast<const float4*>(wr + (size_t)d * NE_ALL);
        float4 w0 = w4[0], w1 = w4[1];
        acc[0] += xv * w0.x; acc[1] += xv * w0.y;
        acc[2] += xv * w0.z; acc[3] += xv * w0.w;
        acc[4] += xv * w1.x; acc[5] += xv * w1.y;
        acc[6] += xv * w1.z; acc[7] += xv * w1.w;
    }
#pragma unroll
    for (int e = 0; e < NE_ALL; e++)
#pragma unroll
        for (int o = 16; o > 0; o >>= 1)
            acc[e] += __shfl_xor_sync(0xffffffffu, acc[e], o);
    if (lane == 0) {
        float m = acc[0]; int idx = 0;
#pragma unroll
        for (int e = 1; e < NE_ALL; e++)
            if (acc[e] > m) { m = acc[e]; idx = e; }
        float s = 0.f;
#pragma unroll
        for (int e = 0; e < NE_ALL; e++) s += expf(acc[e] - m);
        g_scale[gw] = ALPHA_C / s;
        g_eidx[gw]  = idx;
    }
}
__global__ void plan_kernel() {
    __shared__ int cnt[NEXP], offs[NEXP + 1], cur[NEXP];
    int tid = threadIdx.x;
    if (tid < NEXP) cnt[tid] = 0;
    __syncthreads();
    for (int t = tid; t < TOK; t += blockDim.x) {
        int e = g_eidx[t];
        if (e < NEXP) atomicAdd(&cnt[e], 1);
    }
    __syncthreads();
    if (tid == 0) {
        int o = 0;
        for (int e = 0; e < NEXP; e++) { offs[e] = o; cur[e] = o; o += cnt[e]; }
        offs[NEXP] = o;
    }
    __syncthreads();
    for (int t = tid; t < TOK; t += blockDim.x) {
        int e = g_eidx[t];
        if (e < NEXP) g_perm[atomicAdd(&cur[e], 1)] = t;
    }
    if (tid <= NEXP) g_off[tid] = offs[tid];
}

// ---------------------------------------------------------------------------
// Hidden (fp16): H = half( silu(A@Wg) * (A@Wu) )
// z<7 routed (gathered A rows -> Hr), z==7 shared -> Hs.
// Block 128x128 dual-B, BK=64 (4 k16 steps), 3-stage cp.async.
// 8 warps 2x4, warp tile 64x32 per matrix. fp32 accum.
// ---------------------------------------------------------------------------
#define H_AP 72                      // A pitch (halves)
#define H_BP 136                     // B pitch (halves)
#define H_ASZ (128 * H_AP)           // 9216 halves
#define H_BSZ (64 * H_BP)            // 8704 halves
#define H_STG (H_ASZ + 2 * H_BSZ)    // 26624 halves = 53248 B

__global__ __launch_bounds__(NTHREADS, 1)
void hidden_kernel(const __half* __restrict__ A,
                   const __half* __restrict__ Wg,   // [7,K,N]
                   const __half* __restrict__ Wu,
                   const __half* __restrict__ Wsg,  // [K,N]
                   const __half* __restrict__ Wsu,
                   __half* __restrict__ Hr,
                   __half* __restrict__ Hs) {
    extern __shared__ __align__(16) __half smem[];
    const int K = DIMK, N = HIDN;

    int z = blockIdx.z;
    bool routed = (z < NEXP);
    int off, count;
    const __half *BgP, *BuP;
    __half* H;
    if (routed) {
        off = g_off[z]; count = g_off[z + 1] - off;
        BgP = Wg + (size_t)z * K * N;
        BuP = Wu + (size_t)z * K * N;
        H = Hr;
    } else {
        off = 0; count = TOK;
        BgP = Wsg; BuP = Wsu;
        H = Hs;
    }
    int m0 = blockIdx.x * 128;
    if (m0 >= count) return;
    int n0 = blockIdx.y * 128;

    int tid  = threadIdx.x;
    int warp = tid >> 5;
    int wm   = warp >> 2;   // 0..1 (64-row band)
    int wn   = warp & 3;    // 0..3 (32-col band)

    // A source rows: 4 per thread (8 chunks of 8 halves per row, 32 rows / c-step)
    int arow[4];
#pragma unroll
    for (int c = 0; c < 4; c++) {
        int r = (tid + c * NTHREADS) >> 3;
        int rr = m0 + r;
        if (rr >= count) rr = count - 1;
        arow[c] = routed ? g_perm[off + rr] : rr;
    }

    auto load_stage = [&](int kt, int s) {
        __half* As = smem + (size_t)s * H_STG;
        __half* Bg = As + H_ASZ;
        __half* Bu = Bg + H_BSZ;
#pragma unroll
        for (int c = 0; c < 4; c++) {
            int slot = tid + c * NTHREADS;
            int r = slot >> 3;
            int ch = (slot & 7) * 8;
            cp_async16(As + r * H_AP + ch,
                       A + (size_t)arow[c] * K + kt * 64 + ch);
        }
#pragma unroll
        for (int c = 0; c < 8; c++) {
            int slot = tid + c * NTHREADS;       // 0..2047
            int mat = slot >> 10;
            int w   = slot & 1023;
            int br  = w >> 4;                    // 0..63
            int bc  = (w & 15) * 8;              // 0..120
            const __half* src = (mat ? BuP : BgP) + (size_t)(kt * 64 + br) * N + n0 + bc;
            __half* dst = (mat ? Bu : Bg) + br * H_BP + bc;
            cp_async16(dst, src);
        }
        cp_commit();
    };

    wmma::fragment<wmma::accumulator, 16, 16, 16, float> accg[4][2], accu[4][2];
#pragma unroll
    for (int i = 0; i < 4; i++)
#pragma unroll
        for (int j = 0; j < 2; j++) {
            wmma::fill_fragment(accg[i][j], 0.0f);
            wmma::fill_fragment(accu[i][j], 0.0f);
        }

    const int nk = K / 64;   // 16
    load_stage(0, 0);
    load_stage(1, 1);

    for (int kt = 0; kt < nk; kt++) {
        if (kt + 1 < nk) cp_wait<1>(); else cp_wait<0>();
        __syncthreads();

        __half* As = smem + (size_t)(kt % 3) * H_STG;
        __half* Bg = As + H_ASZ;
        __half* Bu = Bg + H_BSZ;

#pragma unroll
        for (int ks = 0; ks < 4; ks++) {
            wmma::fragment<wmma::matrix_a, 16, 16, 16, __half, wmma::row_major> a[4];
            wmma::fragment<wmma::matrix_b, 16, 16, 16, __half, wmma::row_major> bg[2], bu[2];
#pragma unroll
            for (int i = 0; i < 4; i++)
                wmma::load_matrix_sync(a[i], As + (wm * 64 + i * 16) * H_AP + ks * 16, H_AP);
#pragma unroll
            for (int j = 0; j < 2; j++) {
                wmma::load_matrix_sync(bg[j], Bg + (ks * 16) * H_BP + wn * 32 + j * 16, H_BP);
                wmma::load_matrix_sync(bu[j], Bu + (ks * 16) * H_BP + wn * 32 + j * 16, H_BP);
            }
#pragma unroll
            for (int i = 0; i < 4; i++)
#pragma unroll
                for (int j = 0; j < 2; j++) {
                    wmma::mma_sync(accg[i][j], a[i], bg[j], accg[i][j]);
                    wmma::mma_sync(accu[i][j], a[i], bu[j], accu[i][j]);
                }
        }
        if (kt + 2 < nk) load_stage(kt + 2, (kt + 2) % 3);
    }

    // h = silu(g)*u (fp32), stage, then write as fp16
#pragma unroll
    for (int i = 0; i < 4; i++)
#pragma unroll
        for (int j = 0; j < 2; j++)
#pragma unroll
            for (int t = 0; t < accg[i][j].num_elements; t++)
                accg[i][j].x[t] = silu_f(accg[i][j].x[t]) * accu[i][j].x[t];

    __syncthreads();
    float* Cs = reinterpret_cast<float*>(smem);   // 128 x 132 f32 staging
#pragma unroll
    for (int i = 0; i < 4; i++)
#pragma unroll
        for (int j = 0; j < 2; j++)
            wmma::store_matrix_sync(&Cs[(wm * 64 + i * 16) * 132 + wn * 32 + j * 16],
                                    accg[i][j], 132, wmma::mem_row_major);
    __syncthreads();
    for (int lin = tid; lin < 128 * 128; lin += NTHREADS) {
        int r  = lin >> 7;
        int cc = lin & 127;
        if (m0 + r >= count) continue;
        H[(size_t)(off + m0 + r) * N + n0 + cc] = __float2half_rn(Cs[r * 132 + cc]);
    }
}

// ---------------------------------------------------------------------------
// Down (fp16, fused shared+routed): out += via atomicAdd (out pre-zeroed).
// z<7 routed (A=hrh perm rows, per-token scale), z==7 shared (A=hsh).
// Block 128x128, BK=64, 3 stages, 8 warps 2x4, warp 64x32. 2 CTAs/SM.
// ---------------------------------------------------------------------------
#define D_AP 72
#define D_BP 136
#define D_ASZ (128 * D_AP)          // 9216 halves
#define D_BSZ (64 * D_BP)           // 8704 halves
#define D_STG (D_ASZ + D_BSZ)       // 17920 halves = 35840 B

__global__ __launch_bounds__(NTHREADS, 2)
void down_kernel(const __half* __restrict__ Hr,
                 const __half* __restrict__ Hs,
                 const __half* __restrict__ Wd,    // [7,K,N]
                 const __half* __restrict__ Wsd,   // [K,N]
                 float* __restrict__ out) {
    extern __shared__ __align__(16) __half smem[];
    const int K = HIDN, N = DIMK;

    int z = blockIdx.z;
    bool routed = (z < NEXP);
    int off, count;
    const __half *Ap, *Bp;
    if (routed) {
        off = g_off[z]; count = g_off[z + 1] - off;
        Ap = Hr; Bp = Wd + (size_t)z * K * N;
    } else {
        off = 0; count = TOK;
        Ap = Hs; Bp = Wsd;
    }
    int m0 = blockIdx.x * 128;
    if (m0 >= count) return;
    int n0 = blockIdx.y * 128;

    int tid  = threadIdx.x;
    int warp = tid >> 5;
    int wm   = warp >> 2;
    int wn   = warp & 3;

    int arow[4];
#pragma unroll
    for (int c = 0; c < 4; c++) {
        int r = (tid + c * NTHREADS) >> 3;
        int rr = m0 + r;
        if (rr >= count) rr = count - 1;
        arow[c] = off + rr;
    }

    auto load_stage = [&](int kt, int s) {
        __half* As = smem + (size_t)s * D_STG;
        __half* Bs = As + D_ASZ;
#pragma unroll
        for (int c = 0; c < 4; c++) {
            int slot = tid + c * NTHREADS;
            int r = slot >> 3;
            int ch = (slot & 7) * 8;
            cp_async16(As + r * D_AP + ch,
                       Ap + (size_t)arow[c] * K + kt * 64 + ch);
        }
#pragma unroll
        for (int c = 0; c < 4; c++) {
            int slot = tid + c * NTHREADS;       // 0..1023
            int br  = slot >> 4;                 // 0..63
            int bc  = (slot & 15) * 8;
            cp_async16(Bs + br * D_BP + bc,
                       Bp + (size_t)(kt * 64 + br) * N + n0 + bc);
        }
        cp_commit();
    };

    wmma::fragment<wmma::accumulator, 16, 16, 16, float> acc[4][2];
#pragma unroll
    for (int i = 0; i < 4; i++)
#pragma unroll
        for (int j = 0; j < 2; j++)
            wmma::fill_fragment(acc[i][j], 0.0f);

    const int nk = K / 64;   // 64
    load_stage(0, 0);
    load_stage(1, 1);

    for (int kt = 0; kt < nk; kt++) {
        if (kt + 1 < nk) cp_wait<1>(); else cp_wait<0>();
        __syncthreads();

        __half* As = smem + (size_t)(kt % 3) * D_STG;
        __half* Bs = As + D_ASZ;

#pragma unroll
        for (int ks = 0; ks < 4; ks++) {
            wmma::fragment<wmma::matrix_a, 16, 16, 16, __half, wmma::row_major> a[4];
            wmma::fragment<wmma::matrix_b, 16, 16, 16, __half, wmma::row_major> b[2];
#pragma unroll
            for (int i = 0; i < 4; i++)
                wmma::load_matrix_sync(a[i], As + (wm * 64 + i * 16) * D_AP + ks * 16, D_AP);
#pragma unroll
            for (int j = 0; j < 2; j++)
                wmma::load_matrix_sync(b[j], Bs + (ks * 16) * D_BP + wn * 32 + j * 16, D_BP);
#pragma unroll
            for (int i = 0; i < 4; i++)
#pragma unroll
                for (int j = 0; j < 2; j++)
                    wmma::mma_sync(acc[i][j], a[i], b[j], acc[i][j]);
        }
        if (kt + 2 < nk) load_stage(kt + 2, (kt + 2) % 3);
    }

    // stage f32 -> atomicAdd
    __syncthreads();
    float* Cs = reinterpret_cast<float*>(smem);   // 128 x 132
#pragma unroll
    for (int i = 0; i < 4; i++)
#pragma unroll
        for (int j = 0; j < 2; j++)
            wmma::store_matrix_sync(&Cs[(wm * 64 + i * 16) * 132 + wn * 32 + j * 16],
                                    acc[i][j], 132, wmma::mem_row_major);
    __syncthreads();
    for (int lin = tid; lin < 128 * 128; lin += NTHREADS) {
        int r  = lin >> 7;
        int cc = lin & 127;
        if (m0 + r >= count) continue;
        float v = Cs[r * 132 + cc];
        int tok;
        if (routed) {
            tok = g_perm[off + m0 + r];
            v *= g_scale[tok];
        } else {
            tok = m0 + r;
        }
        atomicAdd(&out[(size_t)tok * N + n0 + cc], v);
    }
}

// ---------------------------------------------------------------------------
// Launch
// ---------------------------------------------------------------------------
extern "C" void kernel_launch(void* const* d_in, const int* in_sizes, int n_in,
                              void* d_out, int out_size) {
    const float* x        = (const float*)d_in[0];
    const float* w_router = (const float*)d_in[1];
    const float* w_up     = (const float*)d_in[2];
    const float* w_gate   = (const float*)d_in[3];
    const float* w_down   = (const float*)d_in[4];
    const float* ws_up    = (const float*)d_in[5];
    const float* ws_gate  = (const float*)d_in[6];
    const float* ws_down  = (const float*)d_in[7];
    float* out = (float*)d_out;

    void* p;
    cudaGetSymbolAddress(&p, g_xh);   __half* xh   = (__half*)p;
    cudaGetSymbolAddress(&p, g_hrh);  __half* hrh  = (__half*)p;
    cudaGetSymbolAddress(&p, g_hsh);  __half* hsh  = (__half*)p;
    cudaGetSymbolAddress(&p, g_wgh);  __half* wgh  = (__half*)p;
    cudaGetSymbolAddress(&p, g_wuh);  __half* wuh  = (__half*)p;
    cudaGetSymbolAddress(&p, g_wdh);  __half* wdh  = (__half*)p;
    cudaGetSymbolAddress(&p, g_wsgh); __half* wsgh = (__half*)p;
    cudaGetSymbolAddress(&p, g_wsuh); __half* wsuh = (__half*)p;
    cudaGetSymbolAddress(&p, g_wsdh); __half* wsdh = (__half*)p;

    const int h_smem = 3 * H_STG * 2;   // 159744 B
    const int d_smem = 3 * D_STG * 2;   // 107520 B
    cudaFuncSetAttribute(hidden_kernel, cudaFuncAttributeMaxDynamicSharedMemorySize, h_smem);
    cudaFuncSetAttribute(down_kernel,   cudaFuncAttributeMaxDynamicSharedMemorySize, d_smem);

    router_kernel<<<TOK / 8, 256>>>(x, w_router);
    plan_kernel<<<1, 256>>>();

    // fp32 -> fp16 conversions
    {
        const int T = 256;
        int n8;
        n8 = TOK * DIMK / 8;
        f2h_kernel<<<(n8 + T - 1) / T, T>>>((const float4*)x, (uint4*)xh, n8);
        n8 = NEXP * DIMK * HIDN / 8;
        f2h_kernel<<<(n8 + T - 1) / T, T>>>((const float4*)w_gate, (uint4*)wgh, n8);
        f2h_kernel<<<(n8 + T - 1) / T, T>>>((const float4*)w_up,   (uint4*)wuh, n8);
        f2h_kernel<<<(n8 + T - 1) / T, T>>>((const float4*)w_down, (uint4*)wdh, n8);
        n8 = DIMK * HIDN / 8;
        f2h_kernel<<<(n8 + T - 1) / T, T>>>((const float4*)ws_gate, (uint4*)wsgh, n8);
        f2h_kernel<<<(n8 + T - 1) / T, T>>>((const float4*)ws_up,   (uint4*)wsuh, n8);
        f2h_kernel<<<(n8 + T - 1) / T, T>>>((const float4*)ws_down, (uint4*)wsdh, n8);
    }
    zero4_kernel<<<TOK * DIMK / 4 / 256, 256>>>((float4*)out, TOK * DIMK / 4);

    dim3 grH(TOK / 128, HIDN / 128, NE_ALL);   // 16 x 32 x 8
    hidden_kernel<<<grH, NTHREADS, h_smem>>>(xh, wgh, wuh, wsgh, wsuh, hrh, hsh);

    dim3 grD(TOK / 128, DIMK / 128, NE_ALL);   // 16 x 8 x 8
    down_kernel<<<grD, NTHREADS, d_smem>>>(hrh, hsh, wdh, wsdh, out);
}

// round 8
// speedup vs baseline: 3.9609x; 1.0321x over previous
#include <cuda_runtime.h>
#include <cuda_fp16.h>
#include <mma.h>
#include <math.h>
#include <stdint.h>

using namespace nvcuda;

#define TOK   2048
#define DIMK  1024
#define HIDN  4096
#define NEXP  7
#define NE_ALL 8
#define ALPHA_C 2.0f

// ---------------------------------------------------------------------------
// Scratch
// ---------------------------------------------------------------------------
__device__ int   g_eidx[TOK];
__device__ float g_scale[TOK];
__device__ int   g_perm[TOK];
__device__ int   g_off[NEXP + 1];
__device__ __align__(128) __half g_xh[(size_t)TOK * DIMK];
__device__ __align__(128) __half g_hrh[(size_t)TOK * HIDN];
__device__ __align__(128) __half g_hsh[(size_t)TOK * HIDN];
__device__ __align__(128) __half g_wgh[(size_t)NEXP * DIMK * HIDN];
__device__ __align__(128) __half g_wuh[(size_t)NEXP * DIMK * HIDN];
__device__ __align__(128) __half g_wdh[(size_t)NEXP * HIDN * DIMK];
__device__ __align__(128) __half g_wsgh[(size_t)DIMK * HIDN];
__device__ __align__(128) __half g_wsuh[(size_t)DIMK * HIDN];
__device__ __align__(128) __half g_wsdh[(size_t)HIDN * DIMK];

// ---------------------------------------------------------------------------
// helpers
// ---------------------------------------------------------------------------
__device__ __forceinline__ void cp_async16(void* smem_dst, const void* gmem_src) {
    uint32_t s = (uint32_t)__cvta_generic_to_shared(smem_dst);
    asm volatile("cp.async.cg.shared.global [%0], [%1], 16;\n" :: "r"(s), "l"(gmem_src));
}
__device__ __forceinline__ void cp_commit() { asm volatile("cp.async.commit_group;\n"); }
template <int N> __device__ __forceinline__ void cp_wait() {
    asm volatile("cp.async.wait_group %0;\n" :: "n"(N));
}
__device__ __forceinline__ float silu_f(float v) { return v / (1.0f + expf(-v)); }

__global__ void f2h_kernel(const float4* __restrict__ s, uint4* __restrict__ d, int n8) {
    int i = blockIdx.x * blockDim.x + threadIdx.x;
    if (i >= n8) return;
    float4 v0 = s[2 * i], v1 = s[2 * i + 1];
    __half2 h0 = __floats2half2_rn(v0.x, v0.y);
    __half2 h1 = __floats2half2_rn(v0.z, v0.w);
    __half2 h2 = __floats2half2_rn(v1.x, v1.y);
    __half2 h3 = __floats2half2_rn(v1.z, v1.w);
    uint4 o;
    o.x = *reinterpret_cast<unsigned*>(&h0);
    o.y = *reinterpret_cast<unsigned*>(&h1);
    o.z = *reinterpret_cast<unsigned*>(&h2);
    o.w = *reinterpret_cast<unsigned*>(&h3);
    d[i] = o;
}
__global__ void zero4_kernel(float4* __restrict__ d, int n4) {
    int i = blockIdx.x * blockDim.x + threadIdx.x;
    if (i < n4) d[i] = make_float4(0.f, 0.f, 0.f, 0.f);
}

// ---------------------------------------------------------------------------
// Router (fp32 exact) + plan
// ---------------------------------------------------------------------------
__global__ void router_kernel(const float* __restrict__ x, const float* __restrict__ wr) {
    int gw   = (blockIdx.x * blockDim.x + threadIdx.x) >> 5;
    int lane = threadIdx.x & 31;
    if (gw >= TOK) return;
    const float* xr = x + (size_t)gw * DIMK;
    float acc[NE_ALL];
#pragma unroll
    for (int e = 0; e < NE_ALL; e++) acc[e] = 0.f;
    for (int d = lane; d < DIMK; d += 32) {
        float xv = xr[d];
        const float4* w4 = reinterpret_cast<const float4*>(wr + (size_t)d * NE_ALL);
        float4 w0 = w4[0], w1 = w4[1];
        acc[0] += xv * w0.x; acc[1] += xv * w0.y;
        acc[2] += xv * w0.z; acc[3] += xv * w0.w;
        acc[4] += xv * w1.x; acc[5] += xv * w1.y;
        acc[6] += xv * w1.z; acc[7] += xv * w1.w;
    }
#pragma unroll
    for (int e = 0; e < NE_ALL; e++)
#pragma unroll
        for (int o = 16; o > 0; o >>= 1)
            acc[e] += __shfl_xor_sync(0xffffffffu, acc[e], o);
    if (lane == 0) {
        float m = acc[0]; int idx = 0;
#pragma unroll
        for (int e = 1; e < NE_ALL; e++)
            if (acc[e] > m) { m = acc[e]; idx = e; }
        float s = 0.f;
#pragma unroll
        for (int e = 0; e < NE_ALL; e++) s += expf(acc[e] - m);
        g_scale[gw] = ALPHA_C / s;
        g_eidx[gw]  = idx;
    }
}
__global__ void plan_kernel() {
    __shared__ int cnt[NEXP], offs[NEXP + 1], cur[NEXP];
    int tid = threadIdx.x;
    if (tid < NEXP) cnt[tid] = 0;
    __syncthreads();
    for (int t = tid; t < TOK; t += blockDim.x) {
        int e = g_eidx[t];
        if (e < NEXP) atomicAdd(&cnt[e], 1);
    }
    __syncthreads();
    if (tid == 0) {
        int o = 0;
        for (int e = 0; e < NEXP; e++) { offs[e] = o; cur[e] = o; o += cnt[e]; }
        offs[NEXP] = o;
    }
    __syncthreads();
    for (int t = tid; t < TOK; t += blockDim.x) {
        int e = g_eidx[t];
        if (e < NEXP) g_perm[atomicAdd(&cur[e], 1)] = t;
    }
    if (tid <= NEXP) g_off[tid] = offs[tid];
}

// ---------------------------------------------------------------------------
// Hidden (fp16): H = half( silu(A@Wg) * (A@Wu) )
// 512 threads, block 128x128 dual-B, 16 warps 4x4, warp tile 32x32 per matrix.
// BK=64, 3-stage cp.async, 1 sync per k-tile. fp32 accum.
// z<7 routed (gathered A rows -> Hr), z==7 shared -> Hs.
// ---------------------------------------------------------------------------
#define H_NT 512
#define H_AP 72                      // A pitch (halves)
#define H_BP 136                     // B pitch (halves)
#define H_ASZ (128 * H_AP)           // 9216 halves
#define H_BSZ (64 * H_BP)            // 8704 halves
#define H_STG (H_ASZ + 2 * H_BSZ)    // 26624 halves = 53248 B

__global__ __launch_bounds__(H_NT, 1)
void hidden_kernel(const __half* __restrict__ A,
                   const __half* __restrict__ Wg,
                   const __half* __restrict__ Wu,
                   const __half* __restrict__ Wsg,
                   const __half* __restrict__ Wsu,
                   __half* __restrict__ Hr,
                   __half* __restrict__ Hs) {
    extern __shared__ __align__(16) __half smem[];
    const int K = DIMK, N = HIDN;

    int z = blockIdx.z;
    bool routed = (z < NEXP);
    int off, count;
    const __half *BgP, *BuP;
    __half* H;
    if (routed) {
        off = g_off[z]; count = g_off[z + 1] - off;
        BgP = Wg + (size_t)z * K * N;
        BuP = Wu + (size_t)z * K * N;
        H = Hr;
    } else {
        off = 0; count = TOK;
        BgP = Wsg; BuP = Wsu;
        H = Hs;
    }
    int m0 = blockIdx.x * 128;
    if (m0 >= count) return;
    int n0 = blockIdx.y * 128;

    int tid  = threadIdx.x;
    int warp = tid >> 5;
    int wm   = warp >> 2;   // 0..3 (32-row band)
    int wn   = warp & 3;    // 0..3 (32-col band)

    // A source rows: 2 per thread (8 chunks of 8 halves per 64-half row)
    int arow[2];
#pragma unroll
    for (int c = 0; c < 2; c++) {
        int r = (tid + c * H_NT) >> 3;
        int rr = m0 + r;
        if (rr >= count) rr = count - 1;
        arow[c] = routed ? g_perm[off + rr] : rr;
    }

    auto load_stage = [&](int kt, int s) {
        __half* As = smem + (size_t)s * H_STG;
        __half* Bg = As + H_ASZ;
        __half* Bu = Bg + H_BSZ;
#pragma unroll
        for (int c = 0; c < 2; c++) {
            int slot = tid + c * H_NT;
            int r = slot >> 3;
            int ch = (slot & 7) * 8;
            cp_async16(As + r * H_AP + ch,
                       A + (size_t)arow[c] * K + kt * 64 + ch);
        }
#pragma unroll
        for (int c = 0; c < 4; c++) {
            int slot = tid + c * H_NT;           // 0..2047
            int mat = slot >> 10;
            int w   = slot & 1023;
            int br  = w >> 4;                    // 0..63
            int bc  = (w & 15) * 8;              // 0..120
            const __half* src = (mat ? BuP : BgP) + (size_t)(kt * 64 + br) * N + n0 + bc;
            __half* dst = (mat ? Bu : Bg) + br * H_BP + bc;
            cp_async16(dst, src);
        }
        cp_commit();
    };

    wmma::fragment<wmma::accumulator, 16, 16, 16, float> accg[2][2], accu[2][2];
#pragma unroll
    for (int i = 0; i < 2; i++)
#pragma unroll
        for (int j = 0; j < 2; j++) {
            wmma::fill_fragment(accg[i][j], 0.0f);
            wmma::fill_fragment(accu[i][j], 0.0f);
        }

    const int nk = K / 64;   // 16
    load_stage(0, 0);
    load_stage(1, 1);

    for (int kt = 0; kt < nk; kt++) {
        if (kt + 1 < nk) cp_wait<1>(); else cp_wait<0>();
        __syncthreads();

        __half* As = smem + (size_t)(kt % 3) * H_STG;
        __half* Bg = As + H_ASZ;
        __half* Bu = Bg + H_BSZ;

#pragma unroll
        for (int ks = 0; ks < 4; ks++) {
            wmma::fragment<wmma::matrix_a, 16, 16, 16, __half, wmma::row_major> a[2];
#pragma unroll
            for (int i = 0; i < 2; i++)
                wmma::load_matrix_sync(a[i], As + (wm * 32 + i * 16) * H_AP + ks * 16, H_AP);
#pragma unroll
            for (int j = 0; j < 2; j++) {
                wmma::fragment<wmma::matrix_b, 16, 16, 16, __half, wmma::row_major> bg, bu;
                wmma::load_matrix_sync(bg, Bg + (ks * 16) * H_BP + wn * 32 + j * 16, H_BP);
                wmma::load_matrix_sync(bu, Bu + (ks * 16) * H_BP + wn * 32 + j * 16, H_BP);
#pragma unroll
                for (int i = 0; i < 2; i++) {
                    wmma::mma_sync(accg[i][j], a[i], bg, accg[i][j]);
                    wmma::mma_sync(accu[i][j], a[i], bu, accu[i][j]);
                }
            }
        }
        if (kt + 2 < nk) load_stage(kt + 2, (kt + 2) % 3);
    }

    // h = silu(g)*u (fp32), stage f32, vectorized half2 writes
#pragma unroll
    for (int i = 0; i < 2; i++)
#pragma unroll
        for (int j = 0; j < 2; j++)
#pragma unroll
            for (int t = 0; t < accg[i][j].num_elements; t++)
                accg[i][j].x[t] = silu_f(accg[i][j].x[t]) * accu[i][j].x[t];

    __syncthreads();
    float* Cs = reinterpret_cast<float*>(smem);   // 128 x 132 f32
#pragma unroll
    for (int i = 0; i < 2; i++)
#pragma unroll
        for (int j = 0; j < 2; j++)
            wmma::store_matrix_sync(&Cs[(wm * 32 + i * 16) * 132 + wn * 32 + j * 16],
                                    accg[i][j], 132, wmma::mem_row_major);
    __syncthreads();
    for (int lin = tid; lin < 128 * 64; lin += H_NT) {
        int r  = lin >> 6;
        int c2 = (lin & 63) * 2;
        if (m0 + r >= count) continue;
        __half2 hv = __floats2half2_rn(Cs[r * 132 + c2], Cs[r * 132 + c2 + 1]);
        *reinterpret_cast<__half2*>(&H[(size_t)(off + m0 + r) * N + n0 + c2]) = hv;
    }
}

// ---------------------------------------------------------------------------
// Down (fp16, fused shared+routed): out += via atomicAdd (out pre-zeroed).
// 256 threads, block 128x128, BK=64, 3 stages, 8 warps 2x4, warp 64x32.
// 2 CTAs/SM.
// ---------------------------------------------------------------------------
#define D_NT 256
#define D_AP 72
#define D_BP 136
#define D_ASZ (128 * D_AP)
#define D_BSZ (64 * D_BP)
#define D_STG (D_ASZ + D_BSZ)   // 17920 halves = 35840 B

__global__ __launch_bounds__(D_NT, 2)
void down_kernel(const __half* __restrict__ Hr,
                 const __half* __restrict__ Hs,
                 const __half* __restrict__ Wd,
                 const __half* __restrict__ Wsd,
                 float* __restrict__ out) {
    extern __shared__ __align__(16) __half smem[];
    const int K = HIDN, N = DIMK;

    int z = blockIdx.z;
    bool routed = (z < NEXP);
    int off, count;
    const __half *Ap, *Bp;
    if (routed) {
        off = g_off[z]; count = g_off[z + 1] - off;
        Ap = Hr; Bp = Wd + (size_t)z * K * N;
    } else {
        off = 0; count = TOK;
        Ap = Hs; Bp = Wsd;
    }
    int m0 = blockIdx.x * 128;
    if (m0 >= count) return;
    int n0 = blockIdx.y * 128;

    int tid  = threadIdx.x;
    int warp = tid >> 5;
    int wm   = warp >> 2;
    int wn   = warp & 3;

    int arow[4];
#pragma unroll
    for (int c = 0; c < 4; c++) {
        int r = (tid + c * D_NT) >> 3;
        int rr = m0 + r;
        if (rr >= count) rr = count - 1;
        arow[c] = off + rr;
    }

    auto load_stage = [&](int kt, int s) {
        __half* As = smem + (size_t)s * D_STG;
        __half* Bs = As + D_ASZ;
#pragma unroll
        for (int c = 0; c < 4; c++) {
            int slot = tid + c * D_NT;
            int r = slot >> 3;
            int ch = (slot & 7) * 8;
            cp_async16(As + r * D_AP + ch,
                       Ap + (size_t)arow[c] * K + kt * 64 + ch);
        }
#pragma unroll
        for (int c = 0; c < 4; c++) {
            int slot = tid + c * D_NT;
            int br  = slot >> 4;
            int bc  = (slot & 15) * 8;
            cp_async16(Bs + br * D_BP + bc,
                       Bp + (size_t)(kt * 64 + br) * N + n0 + bc);
        }
        cp_commit();
    };

    wmma::fragment<wmma::accumulator, 16, 16, 16, float> acc[4][2];
#pragma unroll
    for (int i = 0; i < 4; i++)
#pragma unroll
        for (int j = 0; j < 2; j++)
            wmma::fill_fragment(acc[i][j], 0.0f);

    const int nk = K / 64;   // 64
    load_stage(0, 0);
    load_stage(1, 1);

    for (int kt = 0; kt < nk; kt++) {
        if (kt + 1 < nk) cp_wait<1>(); else cp_wait<0>();
        __syncthreads();

        __half* As = smem + (size_t)(kt % 3) * D_STG;
        __half* Bs = As + D_ASZ;

#pragma unroll
        for (int ks = 0; ks < 4; ks++) {
            wmma::fragment<wmma::matrix_a, 16, 16, 16, __half, wmma::row_major> a[4];
            wmma::fragment<wmma::matrix_b, 16, 16, 16, __half, wmma::row_major> b[2];
#pragma unroll
            for (int i = 0; i < 4; i++)
                wmma::load_matrix_sync(a[i], As + (wm * 64 + i * 16) * D_AP + ks * 16, D_AP);
#pragma unroll
            for (int j = 0; j < 2; j++)
                wmma::load_matrix_sync(b[j], Bs + (ks * 16) * D_BP + wn * 32 + j * 16, D_BP);
#pragma unroll
            for (int i = 0; i < 4; i++)
#pragma unroll
                for (int j = 0; j < 2; j++)
                    wmma::mma_sync(acc[i][j], a[i], b[j], acc[i][j]);
        }
        if (kt + 2 < nk) load_stage(kt + 2, (kt + 2) % 3);
    }

    __syncthreads();
    float* Cs = reinterpret_cast<float*>(smem);   // 128 x 132
#pragma unroll
    for (int i = 0; i < 4; i++)
#pragma unroll
        for (int j = 0; j < 2; j++)
            wmma::store_matrix_sync(&Cs[(wm * 64 + i * 16) * 132 + wn * 32 + j * 16],
                                    acc[i][j], 132, wmma::mem_row_major);
    __syncthreads();
    for (int lin = tid; lin < 128 * 128; lin += D_NT) {
        int r  = lin >> 7;
        int cc = lin & 127;
        if (m0 + r >= count) continue;
        float v = Cs[r * 132 + cc];
        int tok;
        if (routed) {
            tok = g_perm[off + m0 + r];
            v *= g_scale[tok];
        } else {
            tok = m0 + r;
        }
        atomicAdd(&out[(size_t)tok * N + n0 + cc], v);
    }
}

// ---------------------------------------------------------------------------
// Launch
// ---------------------------------------------------------------------------
extern "C" void kernel_launch(void* const* d_in, const int* in_sizes, int n_in,
                              void* d_out, int out_size) {
    const float* x        = (const float*)d_in[0];
    const float* w_router = (const float*)d_in[1];
    const float* w_up     = (const float*)d_in[2];
    const float* w_gate   = (const float*)d_in[3];
    const float* w_down   = (const float*)d_in[4];
    const float* ws_up    = (const float*)d_in[5];
    const float* ws_gate  = (const float*)d_in[6];
    const float* ws_down  = (const float*)d_in[7];
    float* out = (float*)d_out;

    void* p;
    cudaGetSymbolAddress(&p, g_xh);   __half* xh   = (__half*)p;
    cudaGetSymbolAddress(&p, g_hrh);  __half* hrh  = (__half*)p;
    cudaGetSymbolAddress(&p, g_hsh);  __half* hsh  = (__half*)p;
    cudaGetSymbolAddress(&p, g_wgh);  __half* wgh  = (__half*)p;
    cudaGetSymbolAddress(&p, g_wuh);  __half* wuh  = (__half*)p;
    cudaGetSymbolAddress(&p, g_wdh);  __half* wdh  = (__half*)p;
    cudaGetSymbolAddress(&p, g_wsgh); __half* wsgh = (__half*)p;
    cudaGetSymbolAddress(&p, g_wsuh); __half* wsuh = (__half*)p;
    cudaGetSymbolAddress(&p, g_wsdh); __half* wsdh = (__half*)p;

    const int h_smem = 3 * H_STG * 2;   // 159744 B
    const int d_smem = 3 * D_STG * 2;   // 107520 B
    cudaFuncSetAttribute(hidden_kernel, cudaFuncAttributeMaxDynamicSharedMemorySize, h_smem);
    cudaFuncSetAttribute(down_kernel,   cudaFuncAttributeMaxDynamicSharedMemorySize, d_smem);

    router_kernel<<<TOK / 8, 256>>>(x, w_router);
    plan_kernel<<<1, 256>>>();

    {
        const int T = 256;
        int n8;
        n8 = TOK * DIMK / 8;
        f2h_kernel<<<(n8 + T - 1) / T, T>>>((const float4*)x, (uint4*)xh, n8);
        n8 = NEXP * DIMK * HIDN / 8;
        f2h_kernel<<<(n8 + T - 1) / T, T>>>((const float4*)w_gate, (uint4*)wgh, n8);
        f2h_kernel<<<(n8 + T - 1) / T, T>>>((const float4*)w_up,   (uint4*)wuh, n8);
        f2h_kernel<<<(n8 + T - 1) / T, T>>>((const float4*)w_down, (uint4*)wdh, n8);
        n8 = DIMK * HIDN / 8;
        f2h_kernel<<<(n8 + T - 1) / T, T>>>((const float4*)ws_gate, (uint4*)wsgh, n8);
        f2h_kernel<<<(n8 + T - 1) / T, T>>>((const float4*)ws_up,   (uint4*)wsuh, n8);
        f2h_kernel<<<(n8 + T - 1) / T, T>>>((const float4*)ws_down, (uint4*)wsdh, n8);
    }
    zero4_kernel<<<TOK * DIMK / 4 / 256, 256>>>((float4*)out, TOK * DIMK / 4);

    dim3 grH(TOK / 128, HIDN / 128, NE_ALL);   // 16 x 32 x 8
    hidden_kernel<<<grH, H_NT, h_smem>>>(xh, wgh, wuh, wsgh, wsuh, hrh, hsh);

    dim3 grD(TOK / 128, DIMK / 128, NE_ALL);   // 16 x 8 x 8
    down_kernel<<<grD, D_NT, d_smem>>>(hrh, hsh, wdh, wsdh, out);
}

// round 9
// speedup vs baseline: 3.9796x; 1.0047x over previous
#include <cuda_runtime.h>
#include <cuda_fp16.h>
#include <mma.h>
#include <math.h>
#include <stdint.h>

using namespace nvcuda;

#define TOK   2048
#define DIMK  1024
#define HIDN  4096
#define NEXP  7
#define NE_ALL 8
#define ALPHA_C 2.0f

// ---------------------------------------------------------------------------
// Scratch
// ---------------------------------------------------------------------------
__device__ int   g_eidx[TOK];
__device__ float g_scale[TOK];
__device__ int   g_perm[TOK];
__device__ int   g_off[NEXP + 1];
__device__ __align__(128) __half g_xh[(size_t)TOK * DIMK];
__device__ __align__(128) __half g_hrh[(size_t)TOK * HIDN];
__device__ __align__(128) __half g_hsh[(size_t)TOK * HIDN];
__device__ __align__(128) __half g_wgh[(size_t)NEXP * DIMK * HIDN];
__device__ __align__(128) __half g_wuh[(size_t)NEXP * DIMK * HIDN];
__device__ __align__(128) __half g_wdh[(size_t)NEXP * HIDN * DIMK];
__device__ __align__(128) __half g_wsgh[(size_t)DIMK * HIDN];
__device__ __align__(128) __half g_wsuh[(size_t)DIMK * HIDN];
__device__ __align__(128) __half g_wsdh[(size_t)HIDN * DIMK];

// ---------------------------------------------------------------------------
// helpers
// ---------------------------------------------------------------------------
__device__ __forceinline__ void cp_async16(void* smem_dst, const void* gmem_src) {
    uint32_t s = (uint32_t)__cvta_generic_to_shared(smem_dst);
    asm volatile("cp.async.cg.shared.global [%0], [%1], 16;\n" :: "r"(s), "l"(gmem_src));
}
__device__ __forceinline__ void cp_commit() { asm volatile("cp.async.commit_group;\n"); }
template <int N> __device__ __forceinline__ void cp_wait() {
    asm volatile("cp.async.wait_group %0;\n" :: "n"(N));
}
__device__ __forceinline__ float silu_f(float v) { return v / (1.0f + expf(-v)); }

__global__ void f2h_kernel(const float4* __restrict__ s, uint4* __restrict__ d, int n8) {
    int i = blockIdx.x * blockDim.x + threadIdx.x;
    if (i >= n8) return;
    float4 v0 = s[2 * i], v1 = s[2 * i + 1];
    __half2 h0 = __floats2half2_rn(v0.x, v0.y);
    __half2 h1 = __floats2half2_rn(v0.z, v0.w);
    __half2 h2 = __floats2half2_rn(v1.x, v1.y);
    __half2 h3 = __floats2half2_rn(v1.z, v1.w);
    uint4 o;
    o.x = *reinterpret_cast<unsigned*>(&h0);
    o.y = *reinterpret_cast<unsigned*>(&h1);
    o.z = *reinterpret_cast<unsigned*>(&h2);
    o.w = *reinterpret_cast<unsigned*>(&h3);
    d[i] = o;
}
__global__ void zero4_kernel(float4* __restrict__ d, int n4) {
    int i = blockIdx.x * blockDim.x + threadIdx.x;
    if (i < n4) d[i] = make_float4(0.f, 0.f, 0.f, 0.f);
}

// ---------------------------------------------------------------------------
// Router (fp32 exact) + plan
// ---------------------------------------------------------------------------
__global__ void router_kernel(const float* __restrict__ x, const float* __restrict__ wr) {
    int gw   = (blockIdx.x * blockDim.x + threadIdx.x) >> 5;
    int lane = threadIdx.x & 31;
    if (gw >= TOK) return;
    const float* xr = x + (size_t)gw * DIMK;
    float acc[NE_ALL];
#pragma unroll
    for (int e = 0; e < NE_ALL; e++) acc[e] = 0.f;
    for (int d = lane; d < DIMK; d += 32) {
        float xv = xr[d];
        const float4* w4 = reinterpret_cast<const float4*>(wr + (size_t)d * NE_ALL);
        float4 w0 = w4[0], w1 = w4[1];
        acc[0] += xv * w0.x; acc[1] += xv * w0.y;
        acc[2] += xv * w0.z; acc[3] += xv * w0.w;
        acc[4] += xv * w1.x; acc[5] += xv * w1.y;
        acc[6] += xv * w1.z; acc[7] += xv * w1.w;
    }
#pragma unroll
    for (int e = 0; e < NE_ALL; e++)
#pragma unroll
        for (int o = 16; o > 0; o >>= 1)
            acc[e] += __shfl_xor_sync(0xffffffffu, acc[e], o);
    if (lane == 0) {
        float m = acc[0]; int idx = 0;
#pragma unroll
        for (int e = 1; e < NE_ALL; e++)
            if (acc[e] > m) { m = acc[e]; idx = e; }
        float s = 0.f;
#pragma unroll
        for (int e = 0; e < NE_ALL; e++) s += expf(acc[e] - m);
        g_scale[gw] = ALPHA_C / s;
        g_eidx[gw]  = idx;
    }
}
__global__ void plan_kernel() {
    __shared__ int cnt[NEXP], offs[NEXP + 1], cur[NEXP];
    int tid = threadIdx.x;
    if (tid < NEXP) cnt[tid] = 0;
    __syncthreads();
    for (int t = tid; t < TOK; t += blockDim.x) {
        int e = g_eidx[t];
        if (e < NEXP) atomicAdd(&cnt[e], 1);
    }
    __syncthreads();
    if (tid == 0) {
        int o = 0;
        for (int e = 0; e < NEXP; e++) { offs[e] = o; cur[e] = o; o += cnt[e]; }
        offs[NEXP] = o;
    }
    __syncthreads();
    for (int t = tid; t < TOK; t += blockDim.x) {
        int e = g_eidx[t];
        if (e < NEXP) g_perm[atomicAdd(&cur[e], 1)] = t;
    }
    if (tid <= NEXP) g_off[tid] = offs[tid];
}

// ---------------------------------------------------------------------------
// Hidden (fp16): H = half( silu(A@Wg) * (A@Wu) )
// 512 threads, block 128x128 dual-B, 16 warps 4x4, warp tile 32x32.
// BK=64, 4-stage cp.async with 2-deep lookahead (loads issued at loop top).
// z<7 routed (gathered A rows -> Hr), z==7 shared -> Hs.
// ---------------------------------------------------------------------------
#define H_NT 512
#define H_AP 72
#define H_BP 136
#define H_ASZ (128 * H_AP)           // 9216 halves
#define H_BSZ (64 * H_BP)            // 8704 halves
#define H_STG (H_ASZ + 2 * H_BSZ)    // 26624 halves = 53248 B

__global__ __launch_bounds__(H_NT, 1)
void hidden_kernel(const __half* __restrict__ A,
                   const __half* __restrict__ Wg,
                   const __half* __restrict__ Wu,
                   const __half* __restrict__ Wsg,
                   const __half* __restrict__ Wsu,
                   __half* __restrict__ Hr,
                   __half* __restrict__ Hs) {
    extern __shared__ __align__(16) __half smem[];
    const int K = DIMK, N = HIDN;

    int z = blockIdx.z;
    bool routed = (z < NEXP);
    int off, count;
    const __half *BgP, *BuP;
    __half* H;
    if (routed) {
        off = g_off[z]; count = g_off[z + 1] - off;
        BgP = Wg + (size_t)z * K * N;
        BuP = Wu + (size_t)z * K * N;
        H = Hr;
    } else {
        off = 0; count = TOK;
        BgP = Wsg; BuP = Wsu;
        H = Hs;
    }
    int m0 = blockIdx.x * 128;
    if (m0 >= count) return;
    int n0 = blockIdx.y * 128;

    int tid  = threadIdx.x;
    int warp = tid >> 5;
    int wm   = warp >> 2;   // 0..3
    int wn   = warp & 3;    // 0..3

    int arow[2];
#pragma unroll
    for (int c = 0; c < 2; c++) {
        int r = (tid + c * H_NT) >> 3;
        int rr = m0 + r;
        if (rr >= count) rr = count - 1;
        arow[c] = routed ? g_perm[off + rr] : rr;
    }

    auto load_stage = [&](int kt, int s) {
        __half* As = smem + (size_t)s * H_STG;
        __half* Bg = As + H_ASZ;
        __half* Bu = Bg + H_BSZ;
#pragma unroll
        for (int c = 0; c < 2; c++) {
            int slot = tid + c * H_NT;
            int r = slot >> 3;
            int ch = (slot & 7) * 8;
            cp_async16(As + r * H_AP + ch,
                       A + (size_t)arow[c] * K + kt * 64 + ch);
        }
#pragma unroll
        for (int c = 0; c < 4; c++) {
            int slot = tid + c * H_NT;
            int mat = slot >> 10;
            int w   = slot & 1023;
            int br  = w >> 4;
            int bc  = (w & 15) * 8;
            const __half* src = (mat ? BuP : BgP) + (size_t)(kt * 64 + br) * N + n0 + bc;
            __half* dst = (mat ? Bu : Bg) + br * H_BP + bc;
            cp_async16(dst, src);
        }
        cp_commit();
    };

    wmma::fragment<wmma::accumulator, 16, 16, 16, float> accg[2][2], accu[2][2];
#pragma unroll
    for (int i = 0; i < 2; i++)
#pragma unroll
        for (int j = 0; j < 2; j++) {
            wmma::fill_fragment(accg[i][j], 0.0f);
            wmma::fill_fragment(accu[i][j], 0.0f);
        }

    const int nk = K / 64;   // 16
    load_stage(0, 0);
    load_stage(1, 1);

    for (int kt = 0; kt < nk; kt++) {
        // 2-deep lookahead: issue k+2 before waiting on k (4 buffers, race-free)
        if (kt + 2 < nk) {
            load_stage(kt + 2, (kt + 2) & 3);
            cp_wait<2>();
        } else if (kt + 1 < nk) {
            cp_wait<1>();
        } else {
            cp_wait<0>();
        }
        __syncthreads();

        __half* As = smem + (size_t)(kt & 3) * H_STG;
        __half* Bg = As + H_ASZ;
        __half* Bu = Bg + H_BSZ;

#pragma unroll
        for (int ks = 0; ks < 4; ks++) {
            wmma::fragment<wmma::matrix_a, 16, 16, 16, __half, wmma::row_major> a[2];
#pragma unroll
            for (int i = 0; i < 2; i++)
                wmma::load_matrix_sync(a[i], As + (wm * 32 + i * 16) * H_AP + ks * 16, H_AP);
#pragma unroll
            for (int j = 0; j < 2; j++) {
                wmma::fragment<wmma::matrix_b, 16, 16, 16, __half, wmma::row_major> bg, bu;
                wmma::load_matrix_sync(bg, Bg + (ks * 16) * H_BP + wn * 32 + j * 16, H_BP);
                wmma::load_matrix_sync(bu, Bu + (ks * 16) * H_BP + wn * 32 + j * 16, H_BP);
#pragma unroll
                for (int i = 0; i < 2; i++) {
                    wmma::mma_sync(accg[i][j], a[i], bg, accg[i][j]);
                    wmma::mma_sync(accu[i][j], a[i], bu, accu[i][j]);
                }
            }
        }
        __syncthreads();
    }

#pragma unroll
    for (int i = 0; i < 2; i++)
#pragma unroll
        for (int j = 0; j < 2; j++)
#pragma unroll
            for (int t = 0; t < accg[i][j].num_elements; t++)
                accg[i][j].x[t] = silu_f(accg[i][j].x[t]) * accu[i][j].x[t];

    float* Cs = reinterpret_cast<float*>(smem);   // 128 x 132 f32
#pragma unroll
    for (int i = 0; i < 2; i++)
#pragma unroll
        for (int j = 0; j < 2; j++)
            wmma::store_matrix_sync(&Cs[(wm * 32 + i * 16) * 132 + wn * 32 + j * 16],
                                    accg[i][j], 132, wmma::mem_row_major);
    __syncthreads();
    for (int lin = tid; lin < 128 * 64; lin += H_NT) {
        int r  = lin >> 6;
        int c2 = (lin & 63) * 2;
        if (m0 + r >= count) continue;
        __half2 hv = __floats2half2_rn(Cs[r * 132 + c2], Cs[r * 132 + c2 + 1]);
        *reinterpret_cast<__half2*>(&H[(size_t)(off + m0 + r) * N + n0 + c2]) = hv;
    }
}

// ---------------------------------------------------------------------------
// Down (fp16, fused shared+routed): out += via atomicAdd (out pre-zeroed).
// 256 threads, block 128x128, BK=64, 3 stages, 8 warps 2x4, warp 64x32.
// 2 CTAs/SM.
// ---------------------------------------------------------------------------
#define D_NT 256
#define D_AP 72
#define D_BP 136
#define D_ASZ (128 * D_AP)
#define D_BSZ (64 * D_BP)
#define D_STG (D_ASZ + D_BSZ)   // 17920 halves = 35840 B

__global__ __launch_bounds__(D_NT, 2)
void down_kernel(const __half* __restrict__ Hr,
                 const __half* __restrict__ Hs,
                 const __half* __restrict__ Wd,
                 const __half* __restrict__ Wsd,
                 float* __restrict__ out) {
    extern __shared__ __align__(16) __half smem[];
    const int K = HIDN, N = DIMK;

    int z = blockIdx.z;
    bool routed = (z < NEXP);
    int off, count;
    const __half *Ap, *Bp;
    if (routed) {
        off = g_off[z]; count = g_off[z + 1] - off;
        Ap = Hr; Bp = Wd + (size_t)z * K * N;
    } else {
        off = 0; count = TOK;
        Ap = Hs; Bp = Wsd;
    }
    int m0 = blockIdx.x * 128;
    if (m0 >= count) return;
    int n0 = blockIdx.y * 128;

    int tid  = threadIdx.x;
    int warp = tid >> 5;
    int wm   = warp >> 2;
    int wn   = warp & 3;

    int arow[4];
#pragma unroll
    for (int c = 0; c < 4; c++) {
        int r = (tid + c * D_NT) >> 3;
        int rr = m0 + r;
        if (rr >= count) rr = count - 1;
        arow[c] = off + rr;
    }

    auto load_stage = [&](int kt, int s) {
        __half* As = smem + (size_t)s * D_STG;
        __half* Bs = As + D_ASZ;
#pragma unroll
        for (int c = 0; c < 4; c++) {
            int slot = tid + c * D_NT;
            int r = slot >> 3;
            int ch = (slot & 7) * 8;
            cp_async16(As + r * D_AP + ch,
                       Ap + (size_t)arow[c] * K + kt * 64 + ch);
        }
#pragma unroll
        for (int c = 0; c < 4; c++) {
            int slot = tid + c * D_NT;
            int br  = slot >> 4;
            int bc  = (slot & 15) * 8;
            cp_async16(Bs + br * D_BP + bc,
                       Bp + (size_t)(kt * 64 + br) * N + n0 + bc);
        }
        cp_commit();
    };

    wmma::fragment<wmma::accumulator, 16, 16, 16, float> acc[4][2];
#pragma unroll
    for (int i = 0; i < 4; i++)
#pragma unroll
        for (int j = 0; j < 2; j++)
            wmma::fill_fragment(acc[i][j], 0.0f);

    const int nk = K / 64;   // 64
    load_stage(0, 0);
    load_stage(1, 1);

    for (int kt = 0; kt < nk; kt++) {
        if (kt + 1 < nk) cp_wait<1>(); else cp_wait<0>();
        __syncthreads();

        __half* As = smem + (size_t)(kt % 3) * D_STG;
        __half* Bs = As + D_ASZ;

#pragma unroll
        for (int ks = 0; ks < 4; ks++) {
            wmma::fragment<wmma::matrix_a, 16, 16, 16, __half, wmma::row_major> a[4];
            wmma::fragment<wmma::matrix_b, 16, 16, 16, __half, wmma::row_major> b[2];
#pragma unroll
            for (int i = 0; i < 4; i++)
                wmma::load_matrix_sync(a[i], As + (wm * 64 + i * 16) * D_AP + ks * 16, D_AP);
#pragma unroll
            for (int j = 0; j < 2; j++)
                wmma::load_matrix_sync(b[j], Bs + (ks * 16) * D_BP + wn * 32 + j * 16, D_BP);
#pragma unroll
            for (int i = 0; i < 4; i++)
#pragma unroll
                for (int j = 0; j < 2; j++)
                    wmma::mma_sync(acc[i][j], a[i], b[j], acc[i][j]);
        }
        if (kt + 2 < nk) load_stage(kt + 2, (kt + 2) % 3);
    }

    __syncthreads();
    float* Cs = reinterpret_cast<float*>(smem);
#pragma unroll
    for (int i = 0; i < 4; i++)
#pragma unroll
        for (int j = 0; j < 2; j++)
            wmma::store_matrix_sync(&Cs[(wm * 64 + i * 16) * 132 + wn * 32 + j * 16],
                                    acc[i][j], 132, wmma::mem_row_major);
    __syncthreads();
    for (int lin = tid; lin < 128 * 128; lin += D_NT) {
        int r  = lin >> 7;
        int cc = lin & 127;
        if (m0 + r >= count) continue;
        float v = Cs[r * 132 + cc];
        int tok;
        if (routed) {
            tok = g_perm[off + m0 + r];
            v *= g_scale[tok];
        } else {
            tok = m0 + r;
        }
        atomicAdd(&out[(size_t)tok * N + n0 + cc], v);
    }
}

// ---------------------------------------------------------------------------
// Launch — two-stream graph: conversions/zero overlap router/plan and hidden.
// ---------------------------------------------------------------------------
extern "C" void kernel_launch(void* const* d_in, const int* in_sizes, int n_in,
                              void* d_out, int out_size) {
    const float* x        = (const float*)d_in[0];
    const float* w_router = (const float*)d_in[1];
    const float* w_up     = (const float*)d_in[2];
    const float* w_gate   = (const float*)d_in[3];
    const float* w_down   = (const float*)d_in[4];
    const float* ws_up    = (const float*)d_in[5];
    const float* ws_gate  = (const float*)d_in[6];
    const float* ws_down  = (const float*)d_in[7];
    float* out = (float*)d_out;

    void* p;
    cudaGetSymbolAddress(&p, g_xh);   __half* xh   = (__half*)p;
    cudaGetSymbolAddress(&p, g_hrh);  __half* hrh  = (__half*)p;
    cudaGetSymbolAddress(&p, g_hsh);  __half* hsh  = (__half*)p;
    cudaGetSymbolAddress(&p, g_wgh);  __half* wgh  = (__half*)p;
    cudaGetSymbolAddress(&p, g_wuh);  __half* wuh  = (__half*)p;
    cudaGetSymbolAddress(&p, g_wdh);  __half* wdh  = (__half*)p;
    cudaGetSymbolAddress(&p, g_wsgh); __half* wsgh = (__half*)p;
    cudaGetSymbolAddress(&p, g_wsuh); __half* wsuh = (__half*)p;
    cudaGetSymbolAddress(&p, g_wsdh); __half* wsdh = (__half*)p;

    const int h_smem = 4 * H_STG * 2;   // 212992 B
    const int d_smem = 3 * D_STG * 2;   // 107520 B
    cudaFuncSetAttribute(hidden_kernel, cudaFuncAttributeMaxDynamicSharedMemorySize, h_smem);
    cudaFuncSetAttribute(down_kernel,   cudaFuncAttributeMaxDynamicSharedMemorySize, d_smem);

    // one-time resource init (host-side only; before the harness's capture call)
    static cudaStream_t s2 = nullptr;
    static cudaEvent_t evFork = nullptr, evGU = nullptr, evD = nullptr;
    if (s2 == nullptr) {
        cudaStreamCreateWithFlags(&s2, cudaStreamNonBlocking);
        cudaEventCreateWithFlags(&evFork, cudaEventDisableTiming);
        cudaEventCreateWithFlags(&evGU,   cudaEventDisableTiming);
        cudaEventCreateWithFlags(&evD,    cudaEventDisableTiming);
    }

    const int T = 256;

    // fork side stream from the default (capture-origin) stream
    cudaEventRecord(evFork, 0);
    cudaStreamWaitEvent(s2, evFork, 0);

    // side stream: conversions + zero
    {
        int n8 = TOK * DIMK / 8;
        f2h_kernel<<<(n8 + T - 1) / T, T, 0, s2>>>((const float4*)x, (uint4*)xh, n8);
        int n8s = DIMK * HIDN / 8;
        f2h_kernel<<<(n8s + T - 1) / T, T, 0, s2>>>((const float4*)ws_gate, (uint4*)wsgh, n8s);
        f2h_kernel<<<(n8s + T - 1) / T, T, 0, s2>>>((const float4*)ws_up,   (uint4*)wsuh, n8s);
        int n8r = NEXP * DIMK * HIDN / 8;
        f2h_kernel<<<(n8r + T - 1) / T, T, 0, s2>>>((const float4*)w_gate, (uint4*)wgh, n8r);
        f2h_kernel<<<(n8r + T - 1) / T, T, 0, s2>>>((const float4*)w_up,   (uint4*)wuh, n8r);
        cudaEventRecord(evGU, s2);
        // down-projection weights + output zero: overlap with hidden GEMM
        f2h_kernel<<<(n8r + T - 1) / T, T, 0, s2>>>((const float4*)w_down, (uint4*)wdh, n8r);
        f2h_kernel<<<(n8s + T - 1) / T, T, 0, s2>>>((const float4*)ws_down, (uint4*)wsdh, n8s);
        zero4_kernel<<<TOK * DIMK / 4 / T, T, 0, s2>>>((float4*)out, TOK * DIMK / 4);
        cudaEventRecord(evD, s2);
    }

    // default stream: router + plan (runs concurrently with conversions)
    router_kernel<<<TOK / 8, 256>>>(x, w_router);
    plan_kernel<<<1, 256>>>();

    // hidden needs xh + gate/up weights
    cudaStreamWaitEvent(0, evGU, 0);
    dim3 grH(TOK / 128, HIDN / 128, NE_ALL);
    hidden_kernel<<<grH, H_NT, h_smem>>>(xh, wgh, wuh, wsgh, wsuh, hrh, hsh);

    // down needs down-weights + zeroed out
    cudaStreamWaitEvent(0, evD, 0);
    dim3 grD(TOK / 128, DIMK / 128, NE_ALL);
    down_kernel<<<grD, D_NT, d_smem>>>(hrh, hsh, wdh, wsdh, out);
}